// round 8
// baseline (speedup 1.0000x reference)
#include <cuda_runtime.h>
#include <cuda_fp16.h>
#include <stdint.h>

// ===========================================================================
// ScaledDotProductAttention R8: HMMA, dependency-free MMA passes
//
//   P  = k0 @ W^T                    [1024,1024]  x3
//   T  = rnn @ P^T                   [16384,1024] x3
//   WVt= (Lt @ k1)^T per batch       [1024,2048]  x3, fused transpose+split
//   QK = T @ Lt^T per batch          [2048,2048]  x3  -> fp32
//   weights = softmax(QK * 0.125)    -> d_out (+ fp16 hi for ctx)
//   ctx = weights @ WVt^T per batch  [2048,1024]  x1 (plain fp16) -> d_out
// ===========================================================================

#define NB 8
static const long long CTX_ELEMS = 8LL * 2048 * 1024;  // 16,777,216

// ---------------- device scratch (allocation-free rule) --------------------
#define NME (8 * 2048 * 1024)
__device__ __align__(128) __half g_rnn_h[NME], g_rnn_l[NME];
__device__ __align__(128) __half g_Lt_h[NME],  g_Lt_l[NME];
__device__ __align__(128) __half g_W_h[1024*1024],   g_W_l[1024*1024];
__device__ __align__(128) __half g_k0_h[1024*1024],  g_k0_l[1024*1024];
__device__ __align__(128) __half g_k1t_h[1024*1024], g_k1t_l[1024*1024];
__device__ __align__(128) __half g_P_h[1024*1024],   g_P_l[1024*1024];
__device__ __align__(128) __half g_T_h[NME], g_T_l[NME];
__device__ __align__(128) __half g_WVt_h[NME], g_WVt_l[NME];
__device__ __align__(128) __half g_w_h[8LL*2048*2048];

// ---------------- helpers --------------------------------------------------
__device__ __forceinline__ uint32_t smem_u32(const void* p) {
    uint32_t a;
    asm("{ .reg .u64 t; cvta.to.shared.u64 t, %1; cvt.u32.u64 %0, t; }"
        : "=r"(a) : "l"(p));
    return a;
}
__device__ __forceinline__ void ldm4(uint32_t (&r)[4], uint32_t a) {
    asm volatile("ldmatrix.sync.aligned.m8n8.x4.shared.b16 {%0,%1,%2,%3}, [%4];"
        : "=r"(r[0]), "=r"(r[1]), "=r"(r[2]), "=r"(r[3]) : "r"(a));
}
__device__ __forceinline__ void mma16816(float* c, const uint32_t* a,
                                         uint32_t b0, uint32_t b1) {
    asm volatile("mma.sync.aligned.m16n8k16.row.col.f32.f16.f16.f32 "
        "{%0,%1,%2,%3}, {%4,%5,%6,%7}, {%8,%9}, {%0,%1,%2,%3};"
        : "+f"(c[0]), "+f"(c[1]), "+f"(c[2]), "+f"(c[3])
        : "r"(a[0]), "r"(a[1]), "r"(a[2]), "r"(a[3]), "r"(b0), "r"(b1));
}
__device__ __forceinline__ void cpasync16(uint32_t s, const void* g) {
    asm volatile("cp.async.cg.shared.global [%0], [%1], 16;" :: "r"(s), "l"(g));
}

// ---------------- fp16 HMMA GEMM (NT=3: hi/lo split, NT=1: plain) ----------
// C[M,N] = A[M,K] @ B[N,K]^T, both K-major. CTA tile 128x128, 8 warps
// (warp tile 32x64), K-tile 32, 2-stage cp.async double buffer.
#define OP_BYTES 10240

// EPI 0: fp32 C.  EPI 1: fp16 hi/lo (Ch, Cl).
// EPI 2: transposed fp16 hi/lo per batch of 2048 rows: out[e, s] (ld 2048).
template <int EPI, int NT>
__global__ __launch_bounds__(256) void gemm_hmma(
    const __half* __restrict__ Ah, const __half* __restrict__ Al,
    const __half* __restrict__ Bh, const __half* __restrict__ Bl,
    float* __restrict__ C, __half* __restrict__ Ch, __half* __restrict__ Cl,
    int K, int ldc, long long sA, long long sB, long long sC)
{
    constexpr int NOPS = (NT == 1) ? 2 : 4;
    constexpr uint32_t STAGE = NOPS * OP_BYTES;
    extern __shared__ char smem[];
    const uint32_t sbase = smem_u32(smem);
    const int tid  = threadIdx.x;
    const int lane = tid & 31, wid = tid >> 5;
    const int wm = wid & 3, wn = wid >> 2;   // warp grid 4(m) x 2(n)
    const long long bz = blockIdx.z;
    Ah += bz * sA; Bh += bz * sB;
    if (NT == 3) { Al += bz * sA; Bl += bz * sB; }
    const int row0 = blockIdx.y * 128;
    const int col0 = blockIdx.x * 128;

    float acc[2][8][4];
#pragma unroll
    for (int i = 0; i < 2; ++i)
#pragma unroll
        for (int j = 0; j < 8; ++j)
#pragma unroll
            for (int q = 0; q < 4; ++q) acc[i][j][q] = 0.0f;

    auto load_stage = [&](int st, int k0) {
        const uint32_t base = sbase + st * STAGE;
#pragma unroll
        for (int j = 0; j < 2 * NOPS; ++j) {
            const int op  = j >> 1;                 // NT3: Ah,Al,Bh,Bl  NT1: Ah,Bh
            const int idx = ((j & 1) << 8) + tid;   // 0..511
            const int r = idx >> 2, c = idx & 3;    // row 0..127, 16B chunk
            const __half* gp;
            bool isA;
            if (NT == 1) { isA = (op == 0); gp = isA ? Ah : Bh; }
            else {
                isA = (op < 2);
                gp = (op == 0) ? Ah : (op == 1) ? Al : (op == 2) ? Bh : Bl;
            }
            const int gr = (isA ? row0 : col0) + r;
            cpasync16(base + op * OP_BYTES + r * 80 + c * 16,
                      gp + (long long)gr * K + k0 + c * 8);
        }
        asm volatile("cp.async.commit_group;");
    };

    const int ntiles = K >> 5;
    load_stage(0, 0);

    for (int kt = 0; kt < ntiles; ++kt) {
        if (kt + 1 < ntiles) {
            load_stage((kt + 1) & 1, (kt + 1) << 5);
            asm volatile("cp.async.wait_group 1;" ::: "memory");
        } else {
            asm volatile("cp.async.wait_group 0;" ::: "memory");
        }
        __syncthreads();

        const uint32_t st = sbase + (kt & 1) * STAGE;
        const uint32_t sAh = st;
        const uint32_t sAl = st + OP_BYTES;                       // NT3 only
        const uint32_t sBh = st + (NT == 1 ? 1 : 2) * OP_BYTES;
        const uint32_t sBl = st + 3 * OP_BYTES;                   // NT3 only
        const uint32_t lrow = (lane & 15) * 80 + (lane >> 4) * 16;

#pragma unroll
        for (int ks = 0; ks < 2; ++ks) {
            // ---- preload ALL fragments for this k-step ----
            uint32_t afh[2][4], afl[2][4];
            uint32_t bfh[4][4], bfl[4][4];
#pragma unroll
            for (int mt = 0; mt < 2; ++mt) {
                const uint32_t ao = (uint32_t)(wm * 32 + mt * 16) * 80 + ks * 32 + lrow;
                ldm4(afh[mt], sAh + ao);
                if (NT == 3) ldm4(afl[mt], sAl + ao);
            }
#pragma unroll
            for (int p = 0; p < 4; ++p) {
                const uint32_t bo = (uint32_t)(wn * 64 + p * 16) * 80 + ks * 32 + lrow;
                ldm4(bfh[p], sBh + bo);
                if (NT == 3) ldm4(bfl[p], sBl + bo);
            }
            // ---- pass 1: hi*hi (16 MMAs, all-distinct accumulators) ----
#pragma unroll
            for (int p = 0; p < 4; ++p)
#pragma unroll
                for (int mt = 0; mt < 2; ++mt) {
                    mma16816(acc[mt][2*p],   afh[mt], bfh[p][0], bfh[p][2]);
                    mma16816(acc[mt][2*p+1], afh[mt], bfh[p][1], bfh[p][3]);
                }
            if (NT == 3) {
                // ---- pass 2: hi*lo ----
#pragma unroll
                for (int p = 0; p < 4; ++p)
#pragma unroll
                    for (int mt = 0; mt < 2; ++mt) {
                        mma16816(acc[mt][2*p],   afh[mt], bfl[p][0], bfl[p][2]);
                        mma16816(acc[mt][2*p+1], afh[mt], bfl[p][1], bfl[p][3]);
                    }
                // ---- pass 3: lo*hi ----
#pragma unroll
                for (int p = 0; p < 4; ++p)
#pragma unroll
                    for (int mt = 0; mt < 2; ++mt) {
                        mma16816(acc[mt][2*p],   afl[mt], bfh[p][0], bfh[p][2]);
                        mma16816(acc[mt][2*p+1], afl[mt], bfh[p][1], bfh[p][3]);
                    }
            }
        }
        __syncthreads();
    }

    const int l4 = lane >> 2, l2 = (lane & 3) * 2;

    if (EPI == 2) {
        // Transposed epilogue: stage hi (then lo) tile in smem, write out[e,s].
        __half* sst = (__half*)smem;          // stride 130 halves per m-row
        const int b  = row0 >> 11;            // batch (2048 rows per batch)
        const int s0 = row0 & 2047;
        __half* outs[2] = {Ch, Cl};
#pragma unroll
        for (int pass = 0; pass < 2; ++pass) {
#pragma unroll
            for (int mt = 0; mt < 2; ++mt) {
#pragma unroll
                for (int nt = 0; nt < 8; ++nt) {
                    const int rl = wm * 32 + mt * 16 + l4;
                    const int cl = wn * 64 + nt * 8 + l2;
                    const float* a = acc[mt][nt];
                    __half2 v0, v1;
                    __half h0 = __float2half(a[0]), h1 = __float2half(a[1]);
                    __half h2 = __float2half(a[2]), h3 = __float2half(a[3]);
                    if (pass == 0) {
                        v0 = __halves2half2(h0, h1);
                        v1 = __halves2half2(h2, h3);
                    } else {
                        v0 = __halves2half2(__float2half(a[0] - __half2float(h0)),
                                            __float2half(a[1] - __half2float(h1)));
                        v1 = __halves2half2(__float2half(a[2] - __half2float(h2)),
                                            __float2half(a[3] - __half2float(h3)));
                    }
                    *(__half2*)&sst[rl * 130 + cl]       = v0;
                    *(__half2*)&sst[(rl + 8) * 130 + cl] = v1;
                }
            }
            __syncthreads();
            __half* op = outs[pass];
#pragma unroll
            for (int j = 0; j < 16; ++j) {
                const int e = j * 8 + wid;
                __half v[4];
#pragma unroll
                for (int q = 0; q < 4; ++q)
                    v[q] = sst[(4 * lane + q) * 130 + e];
                const long long o = (long long)b * (1024LL * 2048) +
                                    (long long)(col0 + e) * 2048 + s0 + 4 * lane;
                *(uint2*)(op + o) = *(uint2*)v;
            }
            __syncthreads();
        }
        return;
    }

#pragma unroll
    for (int mt = 0; mt < 2; ++mt) {
#pragma unroll
        for (int nt = 0; nt < 8; ++nt) {
            const int r  = row0 + wm * 32 + mt * 16 + l4;
            const int cc = col0 + wn * 64 + nt * 8 + l2;
            const long long o0 = bz * sC + (long long)r * ldc + cc;
            const long long o1 = o0 + 8LL * ldc;
            const float* a = acc[mt][nt];
            if (EPI == 0) {
                *(float2*)(C + o0) = make_float2(a[0], a[1]);
                *(float2*)(C + o1) = make_float2(a[2], a[3]);
            } else {
                __half2 hh, ll;
                hh.x = __float2half(a[0]); hh.y = __float2half(a[1]);
                ll.x = __float2half(a[0] - __half2float(hh.x));
                ll.y = __float2half(a[1] - __half2float(hh.y));
                *(__half2*)(Ch + o0) = hh;
                *(__half2*)(Cl + o0) = ll;
                hh.x = __float2half(a[2]); hh.y = __float2half(a[3]);
                ll.x = __float2half(a[2] - __half2float(hh.x));
                ll.y = __float2half(a[3] - __half2float(hh.y));
                *(__half2*)(Ch + o1) = hh;
                *(__half2*)(Cl + o1) = ll;
            }
        }
    }
}

// ---------------- fused fp32 -> hi/lo fp16 split for all 4 inputs ----------
// blocks [0,8192): rnn   [8192,16384): Lt   [16384,16896): W   [16896,17408): k0
__global__ __launch_bounds__(256) void split_all_kernel(
    const float* __restrict__ rnn, const float* __restrict__ Lt,
    const float* __restrict__ W,   const float* __restrict__ k0,
    __half* __restrict__ rnnh, __half* __restrict__ rnnl,
    __half* __restrict__ lth,  __half* __restrict__ ltl,
    __half* __restrict__ wh,   __half* __restrict__ wl,
    __half* __restrict__ k0h,  __half* __restrict__ k0l)
{
    const float* x; __half *h, *l;
    long long blk = blockIdx.x;
    if (blk < 8192)       { x = rnn; h = rnnh; l = rnnl; }
    else if (blk < 16384) { x = Lt;  h = lth;  l = ltl;  blk -= 8192; }
    else if (blk < 16896) { x = W;   h = wh;   l = wl;   blk -= 16384; }
    else                  { x = k0;  h = k0h;  l = k0l;  blk -= 16896; }

    const long long i0 = (blk * 256 + threadIdx.x) * 8;
#pragma unroll
    for (int v = 0; v < 2; ++v) {
        const float4 f = *(const float4*)(x + i0 + v * 4);
        const float ff[4] = {f.x, f.y, f.z, f.w};
        __half hh[4], ll[4];
#pragma unroll
        for (int j = 0; j < 4; ++j) {
            hh[j] = __float2half(ff[j]);
            ll[j] = __float2half(ff[j] - __half2float(hh[j]));
        }
        *(uint2*)(h + i0 + v * 4) = *(uint2*)hh;
        *(uint2*)(l + i0 + v * 4) = *(uint2*)ll;
    }
}

// ---------------- fp32 [R,C] -> transposed hi/lo fp16 [C,R] ----------------
__global__ __launch_bounds__(256) void splitT_kernel(
    const float* __restrict__ in, __half* __restrict__ oh,
    __half* __restrict__ ol, int R, int C)
{
    __shared__ float t[32][33];
    const int c0 = blockIdx.x * 32, r0 = blockIdx.y * 32;
    const int tx = threadIdx.x & 31, ty = threadIdx.x >> 5;  // 32 x 8
#pragma unroll
    for (int i = 0; i < 4; ++i)
        t[ty + 8 * i][tx] = in[(long long)(r0 + ty + 8 * i) * C + c0 + tx];
    __syncthreads();
#pragma unroll
    for (int i = 0; i < 4; ++i) {
        const float v = t[tx][ty + 8 * i];
        const __half h = __float2half(v);
        const long long o = (long long)(c0 + ty + 8 * i) * R + r0 + tx;
        oh[o] = h;
        ol[o] = __float2half(v - __half2float(h));
    }
}

// ---------------- softmax rows (2048) + fp16 hi write ----------------------
__global__ __launch_bounds__(256) void softmax_split_kernel(
    float* __restrict__ data, __half* __restrict__ wh, float scale)
{
    __shared__ float sred[256];
    const int tid = threadIdx.x;
    const long long rb = (long long)blockIdx.x * 2048;
    float* row = data + rb;

    float v[8];
    float m = -1e30f;
#pragma unroll
    for (int i = 0; i < 8; ++i) {
        v[i] = row[i * 256 + tid] * scale;
        m = fmaxf(m, v[i]);
    }
    sred[tid] = m;
    __syncthreads();
    for (int s = 128; s > 0; s >>= 1) {
        if (tid < s) sred[tid] = fmaxf(sred[tid], sred[tid + s]);
        __syncthreads();
    }
    m = sred[0];
    __syncthreads();

    float sum = 0.0f;
#pragma unroll
    for (int i = 0; i < 8; ++i) {
        v[i] = expf(v[i] - m);
        sum += v[i];
    }
    sred[tid] = sum;
    __syncthreads();
    for (int s = 128; s > 0; s >>= 1) {
        if (tid < s) sred[tid] += sred[tid + s];
        __syncthreads();
    }
    const float inv = 1.0f / sred[0];
#pragma unroll
    for (int i = 0; i < 8; ++i) {
        const float w = v[i] * inv;
        row[i * 256 + tid] = w;
        wh[rb + i * 256 + tid] = __float2half(w);
    }
}

// ---------------------------------------------------------------------------
extern "C" void kernel_launch(void* const* d_in, const int* in_sizes, int n_in,
                              void* d_out, int out_size)
{
    const float* Lt   = (const float*)d_in[0];   // [8, 2048, 1024]
    const float* rnn  = (const float*)d_in[1];   // [8, 2048, 1024]
    const float* kern = (const float*)d_in[2];   // [2, 1024, 1024]
    const float* W    = (const float*)d_in[3];   // [1024, 1024]

    float* ctx = (float*)d_out;                  // [8, 2048, 1024]
    float* wts = (float*)d_out + CTX_ELEMS;      // [8, 2048, 2048]

    __half *rnnh, *rnnl, *lth, *ltl, *wWh, *wWl, *k0h, *k0l, *k1th, *k1tl;
    __half *Ph, *Pl, *Th, *Tl, *wvth, *wvtl, *wh;
    cudaGetSymbolAddress((void**)&rnnh, g_rnn_h); cudaGetSymbolAddress((void**)&rnnl, g_rnn_l);
    cudaGetSymbolAddress((void**)&lth,  g_Lt_h);  cudaGetSymbolAddress((void**)&ltl,  g_Lt_l);
    cudaGetSymbolAddress((void**)&wWh,  g_W_h);   cudaGetSymbolAddress((void**)&wWl,  g_W_l);
    cudaGetSymbolAddress((void**)&k0h,  g_k0_h);  cudaGetSymbolAddress((void**)&k0l,  g_k0_l);
    cudaGetSymbolAddress((void**)&k1th, g_k1t_h); cudaGetSymbolAddress((void**)&k1tl, g_k1t_l);
    cudaGetSymbolAddress((void**)&Ph,   g_P_h);   cudaGetSymbolAddress((void**)&Pl,   g_P_l);
    cudaGetSymbolAddress((void**)&Th,   g_T_h);   cudaGetSymbolAddress((void**)&Tl,   g_T_l);
    cudaGetSymbolAddress((void**)&wvth, g_WVt_h); cudaGetSymbolAddress((void**)&wvtl, g_WVt_l);
    cudaGetSymbolAddress((void**)&wh,   g_w_h);

    const int SMEM3 = 2 * 4 * OP_BYTES;  // 81920
    const int SMEM1 = 2 * 2 * OP_BYTES;  // 40960
    cudaFuncSetAttribute(gemm_hmma<0,3>, cudaFuncAttributeMaxDynamicSharedMemorySize, SMEM3);
    cudaFuncSetAttribute(gemm_hmma<1,3>, cudaFuncAttributeMaxDynamicSharedMemorySize, SMEM3);
    cudaFuncSetAttribute(gemm_hmma<2,3>, cudaFuncAttributeMaxDynamicSharedMemorySize, SMEM3);
    cudaFuncSetAttribute(gemm_hmma<0,1>, cudaFuncAttributeMaxDynamicSharedMemorySize, SMEM1);

    // 0) fused splits (launch idx 0) + k1 transpose-split (idx 1)
    split_all_kernel<<<17408, 256>>>(rnn, Lt, W, kern,
                                     rnnh, rnnl, lth, ltl,
                                     wWh, wWl, k0h, k0l);
    splitT_kernel<<<dim3(32, 32, 1), 256>>>(kern + 1024 * 1024, k1th, k1tl, 1024, 1024);

    // 2) P = k0 @ W^T  [1024,1024]
    gemm_hmma<1,3><<<dim3(8, 8, 1), 256, SMEM3>>>(
        k0h, k0l, wWh, wWl, nullptr, Ph, Pl, 1024, 1024, 0, 0, 0);

    // 3) T = rnn @ P^T  [16384,1024]
    gemm_hmma<1,3><<<dim3(8, 128, 1), 256, SMEM3>>>(
        rnnh, rnnl, Ph, Pl, nullptr, Th, Tl, 1024, 1024, 0, 0, 0);

    // 4) WVt = (Lt @ k1)^T per batch  (EPI2: fused transpose + split)
    gemm_hmma<2,3><<<dim3(8, 128, 1), 256, SMEM3>>>(
        lth, ltl, k1th, k1tl, nullptr, wvth, wvtl, 1024, 0, 0, 0, 0);

    // 5) QK = T @ Lt^T per batch -> fp32 wts slab of d_out   (profiled slot)
    gemm_hmma<0,3><<<dim3(16, 16, 8), 256, SMEM3>>>(
        Th, Tl, lth, ltl, wts, nullptr, nullptr, 1024, 2048,
        2048LL * 1024, 2048LL * 1024, 2048LL * 2048);

    // 6) softmax(QK * 0.125) in place + fp16 hi for context GEMM
    softmax_split_kernel<<<16384, 256>>>(wts, wh, 0.125f);

    // 7) ctx = weights @ WVt^T per batch, K=2048, plain fp16 (1 term)
    gemm_hmma<0,1><<<dim3(8, 16, 8), 256, SMEM1>>>(
        wh, nullptr, wvth, nullptr, ctx, nullptr, nullptr, 2048, 1024,
        2048LL * 2048, 1024LL * 2048, 2048LL * 1024);
}

// round 9
// speedup vs baseline: 1.0454x; 1.0454x over previous
#include <cuda_runtime.h>
#include <cuda_fp16.h>
#include <stdint.h>

// ===========================================================================
// ScaledDotProductAttention R9: HMMA x3 with fp16-accumulated cross terms
//
//   P  = k0 @ W^T                    [1024,1024]  x3
//   T  = rnn @ P^T                   [16384,1024] x3
//   WVt= (Lt @ k1)^T per batch       [1024,2048]  x3, fused transpose+split
//   QK = T @ Lt^T per batch          [2048,2048]  x3  -> fp32
//   weights = softmax(QK * 0.125)    -> d_out (+ fp16 hi for ctx)
//   ctx = weights @ WVt^T per batch  [2048,1024]  x1 (plain fp16) -> d_out
//
// x3 = Ah*Bh (fp32 acc) + [Ah*Bl + Al*Bh] (shared fp16 acc, added at epi).
// ===========================================================================

#define NB 8
static const long long CTX_ELEMS = 8LL * 2048 * 1024;  // 16,777,216

// ---------------- device scratch (allocation-free rule) --------------------
#define NME (8 * 2048 * 1024)
__device__ __align__(128) __half g_rnn_h[NME], g_rnn_l[NME];
__device__ __align__(128) __half g_Lt_h[NME],  g_Lt_l[NME];
__device__ __align__(128) __half g_W_h[1024*1024],   g_W_l[1024*1024];
__device__ __align__(128) __half g_k0_h[1024*1024],  g_k0_l[1024*1024];
__device__ __align__(128) __half g_k1t_h[1024*1024], g_k1t_l[1024*1024];
__device__ __align__(128) __half g_P_h[1024*1024],   g_P_l[1024*1024];
__device__ __align__(128) __half g_T_h[NME], g_T_l[NME];
__device__ __align__(128) __half g_WVt_h[NME], g_WVt_l[NME];
__device__ __align__(128) __half g_w_h[8LL*2048*2048];

// ---------------- helpers --------------------------------------------------
__device__ __forceinline__ uint32_t smem_u32(const void* p) {
    uint32_t a;
    asm("{ .reg .u64 t; cvta.to.shared.u64 t, %1; cvt.u32.u64 %0, t; }"
        : "=r"(a) : "l"(p));
    return a;
}
__device__ __forceinline__ void ldm4(uint32_t (&r)[4], uint32_t a) {
    asm volatile("ldmatrix.sync.aligned.m8n8.x4.shared.b16 {%0,%1,%2,%3}, [%4];"
        : "=r"(r[0]), "=r"(r[1]), "=r"(r[2]), "=r"(r[3]) : "r"(a));
}
// fp32-accumulate MMA
__device__ __forceinline__ void mma16816(float* c, const uint32_t* a,
                                         uint32_t b0, uint32_t b1) {
    asm volatile("mma.sync.aligned.m16n8k16.row.col.f32.f16.f16.f32 "
        "{%0,%1,%2,%3}, {%4,%5,%6,%7}, {%8,%9}, {%0,%1,%2,%3};"
        : "+f"(c[0]), "+f"(c[1]), "+f"(c[2]), "+f"(c[3])
        : "r"(a[0]), "r"(a[1]), "r"(a[2]), "r"(a[3]), "r"(b0), "r"(b1));
}
// fp16-accumulate MMA (C/D = 2 x b32 = 4 halves, same lane layout as f32 form)
__device__ __forceinline__ void mma16816h(uint32_t* c, const uint32_t* a,
                                          uint32_t b0, uint32_t b1) {
    asm volatile("mma.sync.aligned.m16n8k16.row.col.f16.f16.f16.f16 "
        "{%0,%1}, {%2,%3,%4,%5}, {%6,%7}, {%0,%1};"
        : "+r"(c[0]), "+r"(c[1])
        : "r"(a[0]), "r"(a[1]), "r"(a[2]), "r"(a[3]), "r"(b0), "r"(b1));
}
__device__ __forceinline__ void cpasync16(uint32_t s, const void* g) {
    asm volatile("cp.async.cg.shared.global [%0], [%1], 16;" :: "r"(s), "l"(g));
}

// ---------------- fp16 HMMA GEMM (NT=3: hi/lo split, NT=1: plain) ----------
// C[M,N] = A[M,K] @ B[N,K]^T, both K-major. CTA tile 128x128, 8 warps
// (warp tile 32x64), K-tile 32, 2-stage cp.async double buffer.
#define OP_BYTES 10240

// EPI 0: fp32 C.  EPI 1: fp16 hi/lo (Ch, Cl).
// EPI 2: transposed fp16 hi/lo per batch of 2048 rows: out[e, s] (ld 2048).
template <int EPI, int NT>
__global__ __launch_bounds__(256, 2) void gemm_hmma(
    const __half* __restrict__ Ah, const __half* __restrict__ Al,
    const __half* __restrict__ Bh, const __half* __restrict__ Bl,
    float* __restrict__ C, __half* __restrict__ Ch, __half* __restrict__ Cl,
    int K, int ldc, long long sA, long long sB, long long sC)
{
    constexpr int NOPS = (NT == 1) ? 2 : 4;
    constexpr uint32_t STAGE = NOPS * OP_BYTES;
    extern __shared__ char smem[];
    const uint32_t sbase = smem_u32(smem);
    const int tid  = threadIdx.x;
    const int lane = tid & 31, wid = tid >> 5;
    const int wm = wid & 3, wn = wid >> 2;   // warp grid 4(m) x 2(n)
    const long long bz = blockIdx.z;
    Ah += bz * sA; Bh += bz * sB;
    if (NT == 3) { Al += bz * sA; Bl += bz * sB; }
    const int row0 = blockIdx.y * 128;
    const int col0 = blockIdx.x * 128;

    float acch[2][8][4];           // hi*hi, fp32 accum
    uint32_t accx[2][8][2];        // cross terms, fp16 accum (half2 pairs)
#pragma unroll
    for (int i = 0; i < 2; ++i)
#pragma unroll
        for (int j = 0; j < 8; ++j) {
#pragma unroll
            for (int q = 0; q < 4; ++q) acch[i][j][q] = 0.0f;
            accx[i][j][0] = 0u; accx[i][j][1] = 0u;
        }

    auto load_stage = [&](int st, int k0) {
        const uint32_t base = sbase + st * STAGE;
#pragma unroll
        for (int j = 0; j < 2 * NOPS; ++j) {
            const int op  = j >> 1;                 // NT3: Ah,Al,Bh,Bl  NT1: Ah,Bh
            const int idx = ((j & 1) << 8) + tid;   // 0..511
            const int r = idx >> 2, c = idx & 3;    // row 0..127, 16B chunk
            const __half* gp;
            bool isA;
            if (NT == 1) { isA = (op == 0); gp = isA ? Ah : Bh; }
            else {
                isA = (op < 2);
                gp = (op == 0) ? Ah : (op == 1) ? Al : (op == 2) ? Bh : Bl;
            }
            const int gr = (isA ? row0 : col0) + r;
            cpasync16(base + op * OP_BYTES + r * 80 + c * 16,
                      gp + (long long)gr * K + k0 + c * 8);
        }
        asm volatile("cp.async.commit_group;");
    };

    const int ntiles = K >> 5;
    load_stage(0, 0);

    for (int kt = 0; kt < ntiles; ++kt) {
        // stage kt is the only pending cp.async group here
        asm volatile("cp.async.wait_group 0;" ::: "memory");
        __syncthreads();   // all warps done with math(kt-1) AND stage kt visible
        if (kt + 1 < ntiles)
            load_stage((kt + 1) & 1, (kt + 1) << 5);  // overwrites stage kt-1: safe

        const uint32_t st = sbase + (kt & 1) * STAGE;
        const uint32_t sAh = st;
        const uint32_t sAl = st + OP_BYTES;                       // NT3 only
        const uint32_t sBh = st + (NT == 1 ? 1 : 2) * OP_BYTES;
        const uint32_t sBl = st + 3 * OP_BYTES;                   // NT3 only
        const uint32_t lrow = (lane & 15) * 80 + (lane >> 4) * 16;

#pragma unroll
        for (int ks = 0; ks < 2; ++ks) {
            uint32_t afh[2][4], afl[2][4];
#pragma unroll
            for (int mt = 0; mt < 2; ++mt) {
                const uint32_t ao = (uint32_t)(wm * 32 + mt * 16) * 80 + ks * 32 + lrow;
                ldm4(afh[mt], sAh + ao);
                if (NT == 3) ldm4(afl[mt], sAl + ao);
            }
#pragma unroll
            for (int p = 0; p < 4; ++p) {
                uint32_t bfh[4], bfl[4];
                const uint32_t bo = (uint32_t)(wn * 64 + p * 16) * 80 + ks * 32 + lrow;
                ldm4(bfh, sBh + bo);
                if (NT == 3) ldm4(bfl, sBl + bo);
                // main term: fp32 accumulate
#pragma unroll
                for (int mt = 0; mt < 2; ++mt) {
                    mma16816(acch[mt][2*p],   afh[mt], bfh[0], bfh[2]);
                    mma16816(acch[mt][2*p+1], afh[mt], bfh[1], bfh[3]);
                }
                if (NT == 3) {
                    // cross terms: fp16 accumulate, 4 distinct dests per pass
#pragma unroll
                    for (int mt = 0; mt < 2; ++mt) {
                        mma16816h(accx[mt][2*p],   afh[mt], bfl[0], bfl[2]);
                        mma16816h(accx[mt][2*p+1], afh[mt], bfl[1], bfl[3]);
                    }
#pragma unroll
                    for (int mt = 0; mt < 2; ++mt) {
                        mma16816h(accx[mt][2*p],   afl[mt], bfh[0], bfh[2]);
                        mma16816h(accx[mt][2*p+1], afl[mt], bfh[1], bfh[3]);
                    }
                }
            }
        }
    }
    __syncthreads();

    // fold fp16 cross accumulators into the fp32 result
    if (NT == 3) {
#pragma unroll
        for (int mt = 0; mt < 2; ++mt)
#pragma unroll
            for (int nt = 0; nt < 8; ++nt) {
                const __half2 x0 = *(const __half2*)&accx[mt][nt][0];
                const __half2 x1 = *(const __half2*)&accx[mt][nt][1];
                acch[mt][nt][0] += __half2float(x0.x);
                acch[mt][nt][1] += __half2float(x0.y);
                acch[mt][nt][2] += __half2float(x1.x);
                acch[mt][nt][3] += __half2float(x1.y);
            }
    }

    const int l4 = lane >> 2, l2 = (lane & 3) * 2;

    if (EPI == 2) {
        // Transposed epilogue: stage hi (then lo) tile in smem, write out[e,s].
        __half* sst = (__half*)smem;          // stride 130 halves per m-row
        const int b  = row0 >> 11;            // batch (2048 rows per batch)
        const int s0 = row0 & 2047;
        __half* outs[2] = {Ch, Cl};
#pragma unroll
        for (int pass = 0; pass < 2; ++pass) {
#pragma unroll
            for (int mt = 0; mt < 2; ++mt) {
#pragma unroll
                for (int nt = 0; nt < 8; ++nt) {
                    const int rl = wm * 32 + mt * 16 + l4;
                    const int cl = wn * 64 + nt * 8 + l2;
                    const float* a = acch[mt][nt];
                    __half2 v0, v1;
                    __half h0 = __float2half(a[0]), h1 = __float2half(a[1]);
                    __half h2 = __float2half(a[2]), h3 = __float2half(a[3]);
                    if (pass == 0) {
                        v0 = __halves2half2(h0, h1);
                        v1 = __halves2half2(h2, h3);
                    } else {
                        v0 = __halves2half2(__float2half(a[0] - __half2float(h0)),
                                            __float2half(a[1] - __half2float(h1)));
                        v1 = __halves2half2(__float2half(a[2] - __half2float(h2)),
                                            __float2half(a[3] - __half2float(h3)));
                    }
                    *(__half2*)&sst[rl * 130 + cl]       = v0;
                    *(__half2*)&sst[(rl + 8) * 130 + cl] = v1;
                }
            }
            __syncthreads();
            __half* op = outs[pass];
#pragma unroll
            for (int j = 0; j < 16; ++j) {
                const int e = j * 8 + wid;
                __half v[4];
#pragma unroll
                for (int q = 0; q < 4; ++q)
                    v[q] = sst[(4 * lane + q) * 130 + e];
                const long long o = (long long)b * (1024LL * 2048) +
                                    (long long)(col0 + e) * 2048 + s0 + 4 * lane;
                *(uint2*)(op + o) = *(uint2*)v;
            }
            __syncthreads();
        }
        return;
    }

#pragma unroll
    for (int mt = 0; mt < 2; ++mt) {
#pragma unroll
        for (int nt = 0; nt < 8; ++nt) {
            const int r  = row0 + wm * 32 + mt * 16 + l4;
            const int cc = col0 + wn * 64 + nt * 8 + l2;
            const long long o0 = bz * sC + (long long)r * ldc + cc;
            const long long o1 = o0 + 8LL * ldc;
            const float* a = acch[mt][nt];
            if (EPI == 0) {
                *(float2*)(C + o0) = make_float2(a[0], a[1]);
                *(float2*)(C + o1) = make_float2(a[2], a[3]);
            } else {
                __half2 hh, ll;
                hh.x = __float2half(a[0]); hh.y = __float2half(a[1]);
                ll.x = __float2half(a[0] - __half2float(hh.x));
                ll.y = __float2half(a[1] - __half2float(hh.y));
                *(__half2*)(Ch + o0) = hh;
                *(__half2*)(Cl + o0) = ll;
                hh.x = __float2half(a[2]); hh.y = __float2half(a[3]);
                ll.x = __float2half(a[2] - __half2float(hh.x));
                ll.y = __float2half(a[3] - __half2float(hh.y));
                *(__half2*)(Ch + o1) = hh;
                *(__half2*)(Cl + o1) = ll;
            }
        }
    }
}

// ---------------- fused fp32 -> hi/lo fp16 split for all 4 inputs ----------
// blocks [0,8192): rnn   [8192,16384): Lt   [16384,16896): W   [16896,17408): k0
__global__ __launch_bounds__(256) void split_all_kernel(
    const float* __restrict__ rnn, const float* __restrict__ Lt,
    const float* __restrict__ W,   const float* __restrict__ k0,
    __half* __restrict__ rnnh, __half* __restrict__ rnnl,
    __half* __restrict__ lth,  __half* __restrict__ ltl,
    __half* __restrict__ wh,   __half* __restrict__ wl,
    __half* __restrict__ k0h,  __half* __restrict__ k0l)
{
    const float* x; __half *h, *l;
    long long blk = blockIdx.x;
    if (blk < 8192)       { x = rnn; h = rnnh; l = rnnl; }
    else if (blk < 16384) { x = Lt;  h = lth;  l = ltl;  blk -= 8192; }
    else if (blk < 16896) { x = W;   h = wh;   l = wl;   blk -= 16384; }
    else                  { x = k0;  h = k0h;  l = k0l;  blk -= 16896; }

    const long long i0 = (blk * 256 + threadIdx.x) * 8;
#pragma unroll
    for (int v = 0; v < 2; ++v) {
        const float4 f = *(const float4*)(x + i0 + v * 4);
        const float ff[4] = {f.x, f.y, f.z, f.w};
        __half hh[4], ll[4];
#pragma unroll
        for (int j = 0; j < 4; ++j) {
            hh[j] = __float2half(ff[j]);
            ll[j] = __float2half(ff[j] - __half2float(hh[j]));
        }
        *(uint2*)(h + i0 + v * 4) = *(uint2*)hh;
        *(uint2*)(l + i0 + v * 4) = *(uint2*)ll;
    }
}

// ---------------- fp32 [R,C] -> transposed hi/lo fp16 [C,R] ----------------
__global__ __launch_bounds__(256) void splitT_kernel(
    const float* __restrict__ in, __half* __restrict__ oh,
    __half* __restrict__ ol, int R, int C)
{
    __shared__ float t[32][33];
    const int c0 = blockIdx.x * 32, r0 = blockIdx.y * 32;
    const int tx = threadIdx.x & 31, ty = threadIdx.x >> 5;  // 32 x 8
#pragma unroll
    for (int i = 0; i < 4; ++i)
        t[ty + 8 * i][tx] = in[(long long)(r0 + ty + 8 * i) * C + c0 + tx];
    __syncthreads();
#pragma unroll
    for (int i = 0; i < 4; ++i) {
        const float v = t[tx][ty + 8 * i];
        const __half h = __float2half(v);
        const long long o = (long long)(c0 + ty + 8 * i) * R + r0 + tx;
        oh[o] = h;
        ol[o] = __float2half(v - __half2float(h));
    }
}

// ---------------- softmax rows (2048) + fp16 hi write ----------------------
__global__ __launch_bounds__(256) void softmax_split_kernel(
    float* __restrict__ data, __half* __restrict__ wh, float scale)
{
    __shared__ float sred[256];
    const int tid = threadIdx.x;
    const long long rb = (long long)blockIdx.x * 2048;
    float* row = data + rb;

    float v[8];
    float m = -1e30f;
#pragma unroll
    for (int i = 0; i < 8; ++i) {
        v[i] = row[i * 256 + tid] * scale;
        m = fmaxf(m, v[i]);
    }
    sred[tid] = m;
    __syncthreads();
    for (int s = 128; s > 0; s >>= 1) {
        if (tid < s) sred[tid] = fmaxf(sred[tid], sred[tid + s]);
        __syncthreads();
    }
    m = sred[0];
    __syncthreads();

    float sum = 0.0f;
#pragma unroll
    for (int i = 0; i < 8; ++i) {
        v[i] = expf(v[i] - m);
        sum += v[i];
    }
    sred[tid] = sum;
    __syncthreads();
    for (int s = 128; s > 0; s >>= 1) {
        if (tid < s) sred[tid] += sred[tid + s];
        __syncthreads();
    }
    const float inv = 1.0f / sred[0];
#pragma unroll
    for (int i = 0; i < 8; ++i) {
        const float w = v[i] * inv;
        row[i * 256 + tid] = w;
        wh[rb + i * 256 + tid] = __float2half(w);
    }
}

// ---------------------------------------------------------------------------
extern "C" void kernel_launch(void* const* d_in, const int* in_sizes, int n_in,
                              void* d_out, int out_size)
{
    const float* Lt   = (const float*)d_in[0];   // [8, 2048, 1024]
    const float* rnn  = (const float*)d_in[1];   // [8, 2048, 1024]
    const float* kern = (const float*)d_in[2];   // [2, 1024, 1024]
    const float* W    = (const float*)d_in[3];   // [1024, 1024]

    float* ctx = (float*)d_out;                  // [8, 2048, 1024]
    float* wts = (float*)d_out + CTX_ELEMS;      // [8, 2048, 2048]

    __half *rnnh, *rnnl, *lth, *ltl, *wWh, *wWl, *k0h, *k0l, *k1th, *k1tl;
    __half *Ph, *Pl, *Th, *Tl, *wvth, *wvtl, *wh;
    cudaGetSymbolAddress((void**)&rnnh, g_rnn_h); cudaGetSymbolAddress((void**)&rnnl, g_rnn_l);
    cudaGetSymbolAddress((void**)&lth,  g_Lt_h);  cudaGetSymbolAddress((void**)&ltl,  g_Lt_l);
    cudaGetSymbolAddress((void**)&wWh,  g_W_h);   cudaGetSymbolAddress((void**)&wWl,  g_W_l);
    cudaGetSymbolAddress((void**)&k0h,  g_k0_h);  cudaGetSymbolAddress((void**)&k0l,  g_k0_l);
    cudaGetSymbolAddress((void**)&k1th, g_k1t_h); cudaGetSymbolAddress((void**)&k1tl, g_k1t_l);
    cudaGetSymbolAddress((void**)&Ph,   g_P_h);   cudaGetSymbolAddress((void**)&Pl,   g_P_l);
    cudaGetSymbolAddress((void**)&Th,   g_T_h);   cudaGetSymbolAddress((void**)&Tl,   g_T_l);
    cudaGetSymbolAddress((void**)&wvth, g_WVt_h); cudaGetSymbolAddress((void**)&wvtl, g_WVt_l);
    cudaGetSymbolAddress((void**)&wh,   g_w_h);

    const int SMEM3 = 2 * 4 * OP_BYTES;  // 81920
    const int SMEM1 = 2 * 2 * OP_BYTES;  // 40960
    cudaFuncSetAttribute(gemm_hmma<0,3>, cudaFuncAttributeMaxDynamicSharedMemorySize, SMEM3);
    cudaFuncSetAttribute(gemm_hmma<1,3>, cudaFuncAttributeMaxDynamicSharedMemorySize, SMEM3);
    cudaFuncSetAttribute(gemm_hmma<2,3>, cudaFuncAttributeMaxDynamicSharedMemorySize, SMEM3);
    cudaFuncSetAttribute(gemm_hmma<0,1>, cudaFuncAttributeMaxDynamicSharedMemorySize, SMEM1);

    // 0) fused splits + k1 transpose-split
    split_all_kernel<<<17408, 256>>>(rnn, Lt, W, kern,
                                     rnnh, rnnl, lth, ltl,
                                     wWh, wWl, k0h, k0l);
    splitT_kernel<<<dim3(32, 32, 1), 256>>>(kern + 1024 * 1024, k1th, k1tl, 1024, 1024);

    // 2) P = k0 @ W^T  [1024,1024]
    gemm_hmma<1,3><<<dim3(8, 8, 1), 256, SMEM3>>>(
        k0h, k0l, wWh, wWl, nullptr, Ph, Pl, 1024, 1024, 0, 0, 0);

    // 3) T = rnn @ P^T  [16384,1024]
    gemm_hmma<1,3><<<dim3(8, 128, 1), 256, SMEM3>>>(
        rnnh, rnnl, Ph, Pl, nullptr, Th, Tl, 1024, 1024, 0, 0, 0);

    // 4) WVt = (Lt @ k1)^T per batch  (EPI2: fused transpose + split)
    gemm_hmma<2,3><<<dim3(8, 128, 1), 256, SMEM3>>>(
        lth, ltl, k1th, k1tl, nullptr, wvth, wvtl, 1024, 0, 0, 0, 0);

    // 5) QK = T @ Lt^T per batch -> fp32 wts slab of d_out
    gemm_hmma<0,3><<<dim3(16, 16, 8), 256, SMEM3>>>(
        Th, Tl, lth, ltl, wts, nullptr, nullptr, 1024, 2048,
        2048LL * 1024, 2048LL * 1024, 2048LL * 2048);

    // 6) softmax(QK * 0.125) in place + fp16 hi for context GEMM
    softmax_split_kernel<<<16384, 256>>>(wts, wh, 0.125f);

    // 7) ctx = weights @ WVt^T per batch, K=2048, plain fp16 (1 term)
    gemm_hmma<0,1><<<dim3(8, 16, 8), 256, SMEM1>>>(
        wh, nullptr, wvth, nullptr, ctx, nullptr, nullptr, 2048, 1024,
        2048LL * 2048, 1024LL * 2048, 2048LL * 1024);
}

// round 11
// speedup vs baseline: 1.1778x; 1.1267x over previous
#include <cuda_runtime.h>
#include <cuda_fp16.h>
#include <stdint.h>

// ===========================================================================
// ScaledDotProductAttention R10: error-budgeted term counts per GEMM
//
//   P  = k0 @ W^T                    [1024,1024]  x3   (logit path)
//   T  = rnn @ P^T                   [16384,1024] x3   (logit path)
//   WVt= (Lt @ k1)^T per batch       [1024,2048]  x1   (post-softmax path)
//   QK = T @ Lt^T per batch          [2048,2048]  x3  -> fp32 (logit path)
//   weights = softmax(QK * 0.125)    -> d_out (+ fp16 hi for ctx)
//   ctx = weights @ WVt^T per batch  [2048,1024]  x1 -> d_out
//
// x3 = Ah*Bh (fp32 acc) + [Ah*Bl + Al*Bh] (shared fp16 acc, added at epi).
// ===========================================================================

#define NB 8
static const long long CTX_ELEMS = 8LL * 2048 * 1024;  // 16,777,216

// ---------------- device scratch (allocation-free rule) --------------------
#define NME (8 * 2048 * 1024)
__device__ __align__(128) __half g_rnn_h[NME], g_rnn_l[NME];
__device__ __align__(128) __half g_Lt_h[NME],  g_Lt_l[NME];
__device__ __align__(128) __half g_W_h[1024*1024],   g_W_l[1024*1024];
__device__ __align__(128) __half g_k0_h[1024*1024],  g_k0_l[1024*1024];
__device__ __align__(128) __half g_k1t_h[1024*1024], g_k1t_l[1024*1024];
__device__ __align__(128) __half g_P_h[1024*1024],   g_P_l[1024*1024];
__device__ __align__(128) __half g_T_h[NME], g_T_l[NME];
__device__ __align__(128) __half g_WVt_h[NME];
__device__ __align__(128) __half g_w_h[8LL*2048*2048];

// ---------------- helpers --------------------------------------------------
__device__ __forceinline__ uint32_t smem_u32(const void* p) {
    uint32_t a;
    asm("{ .reg .u64 t; cvta.to.shared.u64 t, %1; cvt.u32.u64 %0, t; }"
        : "=r"(a) : "l"(p));
    return a;
}
__device__ __forceinline__ void ldm4(uint32_t (&r)[4], uint32_t a) {
    asm volatile("ldmatrix.sync.aligned.m8n8.x4.shared.b16 {%0,%1,%2,%3}, [%4];"
        : "=r"(r[0]), "=r"(r[1]), "=r"(r[2]), "=r"(r[3]) : "r"(a));
}
// fp32-accumulate MMA
__device__ __forceinline__ void mma16816(float* c, const uint32_t* a,
                                         uint32_t b0, uint32_t b1) {
    asm volatile("mma.sync.aligned.m16n8k16.row.col.f32.f16.f16.f32 "
        "{%0,%1,%2,%3}, {%4,%5,%6,%7}, {%8,%9}, {%0,%1,%2,%3};"
        : "+f"(c[0]), "+f"(c[1]), "+f"(c[2]), "+f"(c[3])
        : "r"(a[0]), "r"(a[1]), "r"(a[2]), "r"(a[3]), "r"(b0), "r"(b1));
}
// fp16-accumulate MMA (cross terms; small relative magnitude)
__device__ __forceinline__ void mma16816h(uint32_t* c, const uint32_t* a,
                                          uint32_t b0, uint32_t b1) {
    asm volatile("mma.sync.aligned.m16n8k16.row.col.f16.f16.f16.f16 "
        "{%0,%1}, {%2,%3,%4,%5}, {%6,%7}, {%0,%1};"
        : "+r"(c[0]), "+r"(c[1])
        : "r"(a[0]), "r"(a[1]), "r"(a[2]), "r"(a[3]), "r"(b0), "r"(b1));
}
__device__ __forceinline__ void cpasync16(uint32_t s, const void* g) {
    asm volatile("cp.async.cg.shared.global [%0], [%1], 16;" :: "r"(s), "l"(g));
}

// ---------------- fp16 HMMA GEMM (NT=3: hi/lo split, NT=1: plain) ----------
// C[M,N] = A[M,K] @ B[N,K]^T, both K-major. CTA tile 128x128, 8 warps
// (warp tile 32x64), K-tile 32, 2-stage cp.async double buffer.
#define OP_BYTES 10240

// EPI 0: fp32 C.  EPI 1: fp16 hi/lo (Ch, Cl).
// EPI 2: transposed fp16 per batch of 2048 rows: out[e, s] (ld 2048);
//        writes hi+lo when NT==3, hi only when NT==1.
template <int EPI, int NT>
__global__ __launch_bounds__(256, 2) void gemm_hmma(
    const __half* __restrict__ Ah, const __half* __restrict__ Al,
    const __half* __restrict__ Bh, const __half* __restrict__ Bl,
    float* __restrict__ C, __half* __restrict__ Ch, __half* __restrict__ Cl,
    int K, int ldc, long long sA, long long sB, long long sC)
{
    constexpr int NOPS = (NT == 1) ? 2 : 4;
    constexpr uint32_t STAGE = NOPS * OP_BYTES;
    extern __shared__ char smem[];
    const uint32_t sbase = smem_u32(smem);
    const int tid  = threadIdx.x;
    const int lane = tid & 31, wid = tid >> 5;
    const int wm = wid & 3, wn = wid >> 2;   // warp grid 4(m) x 2(n)
    const long long bz = blockIdx.z;
    Ah += bz * sA; Bh += bz * sB;
    if (NT == 3) { Al += bz * sA; Bl += bz * sB; }
    const int row0 = blockIdx.y * 128;
    const int col0 = blockIdx.x * 128;

    float acch[2][8][4];           // hi*hi, fp32 accum
    uint32_t accx[2][8][2];        // cross terms, fp16 accum (half2 pairs)
#pragma unroll
    for (int i = 0; i < 2; ++i)
#pragma unroll
        for (int j = 0; j < 8; ++j) {
#pragma unroll
            for (int q = 0; q < 4; ++q) acch[i][j][q] = 0.0f;
            accx[i][j][0] = 0u; accx[i][j][1] = 0u;
        }

    auto load_stage = [&](int st, int k0) {
        const uint32_t base = sbase + st * STAGE;
#pragma unroll
        for (int j = 0; j < 2 * NOPS; ++j) {
            const int op  = j >> 1;                 // NT3: Ah,Al,Bh,Bl  NT1: Ah,Bh
            const int idx = ((j & 1) << 8) + tid;   // 0..511
            const int r = idx >> 2, c = idx & 3;    // row 0..127, 16B chunk
            const __half* gp;
            bool isA;
            if (NT == 1) { isA = (op == 0); gp = isA ? Ah : Bh; }
            else {
                isA = (op < 2);
                gp = (op == 0) ? Ah : (op == 1) ? Al : (op == 2) ? Bh : Bl;
            }
            const int gr = (isA ? row0 : col0) + r;
            cpasync16(base + op * OP_BYTES + r * 80 + c * 16,
                      gp + (long long)gr * K + k0 + c * 8);
        }
        asm volatile("cp.async.commit_group;");
    };

    const int ntiles = K >> 5;
    load_stage(0, 0);

    for (int kt = 0; kt < ntiles; ++kt) {
        asm volatile("cp.async.wait_group 0;" ::: "memory");
        __syncthreads();   // math(kt-1) done everywhere AND stage kt visible
        if (kt + 1 < ntiles)
            load_stage((kt + 1) & 1, (kt + 1) << 5);  // overwrites stage kt-1: safe

        const uint32_t st = sbase + (kt & 1) * STAGE;
        const uint32_t sAh = st;
        const uint32_t sAl = st + OP_BYTES;                       // NT3 only
        const uint32_t sBh = st + (NT == 1 ? 1 : 2) * OP_BYTES;
        const uint32_t sBl = st + 3 * OP_BYTES;                   // NT3 only
        const uint32_t lrow = (lane & 15) * 80 + (lane >> 4) * 16;

#pragma unroll
        for (int ks = 0; ks < 2; ++ks) {
            uint32_t afh[2][4], afl[2][4];
#pragma unroll
            for (int mt = 0; mt < 2; ++mt) {
                const uint32_t ao = (uint32_t)(wm * 32 + mt * 16) * 80 + ks * 32 + lrow;
                ldm4(afh[mt], sAh + ao);
                if (NT == 3) ldm4(afl[mt], sAl + ao);
            }
#pragma unroll
            for (int p = 0; p < 4; ++p) {
                uint32_t bfh[4], bfl[4];
                const uint32_t bo = (uint32_t)(wn * 64 + p * 16) * 80 + ks * 32 + lrow;
                ldm4(bfh, sBh + bo);
                if (NT == 3) ldm4(bfl, sBl + bo);
                // main term: fp32 accumulate
#pragma unroll
                for (int mt = 0; mt < 2; ++mt) {
                    mma16816(acch[mt][2*p],   afh[mt], bfh[0], bfh[2]);
                    mma16816(acch[mt][2*p+1], afh[mt], bfh[1], bfh[3]);
                }
                if (NT == 3) {
                    // cross terms: fp16 accumulate
#pragma unroll
                    for (int mt = 0; mt < 2; ++mt) {
                        mma16816h(accx[mt][2*p],   afh[mt], bfl[0], bfl[2]);
                        mma16816h(accx[mt][2*p+1], afh[mt], bfl[1], bfl[3]);
                    }
#pragma unroll
                    for (int mt = 0; mt < 2; ++mt) {
                        mma16816h(accx[mt][2*p],   afl[mt], bfh[0], bfh[2]);
                        mma16816h(accx[mt][2*p+1], afl[mt], bfh[1], bfh[3]);
                    }
                }
            }
        }
    }
    __syncthreads();

    // fold fp16 cross accumulators into the fp32 result
    if (NT == 3) {
#pragma unroll
        for (int mt = 0; mt < 2; ++mt)
#pragma unroll
            for (int nt = 0; nt < 8; ++nt) {
                const __half2 x0 = *(const __half2*)&accx[mt][nt][0];
                const __half2 x1 = *(const __half2*)&accx[mt][nt][1];
                acch[mt][nt][0] += __half2float(x0.x);
                acch[mt][nt][1] += __half2float(x0.y);
                acch[mt][nt][2] += __half2float(x1.x);
                acch[mt][nt][3] += __half2float(x1.y);
            }
    }

    const int l4 = lane >> 2, l2 = (lane & 3) * 2;

    if (EPI == 2) {
        // Transposed epilogue: stage tile in smem, write out[e,s].
        constexpr int NPASS = (NT == 3) ? 2 : 1;   // hi (+ lo if split output)
        __half* sst = (__half*)smem;          // stride 130 halves per m-row
        const int b  = row0 >> 11;            // batch (2048 rows per batch)
        const int s0 = row0 & 2047;
        __half* outs[2] = {Ch, Cl};
#pragma unroll
        for (int pass = 0; pass < NPASS; ++pass) {
#pragma unroll
            for (int mt = 0; mt < 2; ++mt) {
#pragma unroll
                for (int nt = 0; nt < 8; ++nt) {
                    const int rl = wm * 32 + mt * 16 + l4;
                    const int cl = wn * 64 + nt * 8 + l2;
                    const float* a = acch[mt][nt];
                    __half2 v0, v1;
                    __half h0 = __float2half(a[0]), h1 = __float2half(a[1]);
                    __half h2 = __float2half(a[2]), h3 = __float2half(a[3]);
                    if (pass == 0) {
                        v0 = __halves2half2(h0, h1);
                        v1 = __halves2half2(h2, h3);
                    } else {
                        v0 = __halves2half2(__float2half(a[0] - __half2float(h0)),
                                            __float2half(a[1] - __half2float(h1)));
                        v1 = __halves2half2(__float2half(a[2] - __half2float(h2)),
                                            __float2half(a[3] - __half2float(h3)));
                    }
                    *(__half2*)&sst[rl * 130 + cl]       = v0;
                    *(__half2*)&sst[(rl + 8) * 130 + cl] = v1;
                }
            }
            __syncthreads();
            __half* op = outs[pass];
#pragma unroll
            for (int j = 0; j < 16; ++j) {
                const int e = j * 8 + wid;
                __half v[4];
#pragma unroll
                for (int q = 0; q < 4; ++q)
                    v[q] = sst[(4 * lane + q) * 130 + e];
                const long long o = (long long)b * (1024LL * 2048) +
                                    (long long)(col0 + e) * 2048 + s0 + 4 * lane;
                *(uint2*)(op + o) = *(uint2*)v;
            }
            __syncthreads();
        }
        return;
    }

#pragma unroll
    for (int mt = 0; mt < 2; ++mt) {
#pragma unroll
        for (int nt = 0; nt < 8; ++nt) {
            const int r  = row0 + wm * 32 + mt * 16 + l4;
            const int cc = col0 + wn * 64 + nt * 8 + l2;
            const long long o0 = bz * sC + (long long)r * ldc + cc;
            const long long o1 = o0 + 8LL * ldc;
            const float* a = acch[mt][nt];
            if (EPI == 0) {
                *(float2*)(C + o0) = make_float2(a[0], a[1]);
                *(float2*)(C + o1) = make_float2(a[2], a[3]);
            } else {
                __half2 hh, ll;
                hh.x = __float2half(a[0]); hh.y = __float2half(a[1]);
                ll.x = __float2half(a[0] - __half2float(hh.x));
                ll.y = __float2half(a[1] - __half2float(hh.y));
                *(__half2*)(Ch + o0) = hh;
                *(__half2*)(Cl + o0) = ll;
                hh.x = __float2half(a[2]); hh.y = __float2half(a[3]);
                ll.x = __float2half(a[2] - __half2float(hh.x));
                ll.y = __float2half(a[3] - __half2float(hh.y));
                *(__half2*)(Ch + o1) = hh;
                *(__half2*)(Cl + o1) = ll;
            }
        }
    }
}

// ---------------- fused fp32 -> hi/lo fp16 split for all 4 inputs ----------
// blocks [0,8192): rnn   [8192,16384): Lt   [16384,16896): W   [16896,17408): k0
__global__ __launch_bounds__(256) void split_all_kernel(
    const float* __restrict__ rnn, const float* __restrict__ Lt,
    const float* __restrict__ W,   const float* __restrict__ k0,
    __half* __restrict__ rnnh, __half* __restrict__ rnnl,
    __half* __restrict__ lth,  __half* __restrict__ ltl,
    __half* __restrict__ wh,   __half* __restrict__ wl,
    __half* __restrict__ k0h,  __half* __restrict__ k0l)
{
    const float* x; __half *h, *l;
    long long blk = blockIdx.x;
    if (blk < 8192)       { x = rnn; h = rnnh; l = rnnl; }
    else if (blk < 16384) { x = Lt;  h = lth;  l = ltl;  blk -= 8192; }
    else if (blk < 16896) { x = W;   h = wh;   l = wl;   blk -= 16384; }
    else                  { x = k0;  h = k0h;  l = k0l;  blk -= 16896; }

    const long long i0 = (blk * 256 + threadIdx.x) * 8;
#pragma unroll
    for (int v = 0; v < 2; ++v) {
        const float4 f = *(const float4*)(x + i0 + v * 4);
        const float ff[4] = {f.x, f.y, f.z, f.w};
        __half hh[4], ll[4];
#pragma unroll
        for (int j = 0; j < 4; ++j) {
            hh[j] = __float2half(ff[j]);
            ll[j] = __float2half(ff[j] - __half2float(hh[j]));
        }
        *(uint2*)(h + i0 + v * 4) = *(uint2*)hh;
        *(uint2*)(l + i0 + v * 4) = *(uint2*)ll;
    }
}

// ---------------- fp32 [R,C] -> transposed fp16 hi [C,R] -------------------
__global__ __launch_bounds__(256) void splitT_kernel(
    const float* __restrict__ in, __half* __restrict__ oh, int R, int C)
{
    __shared__ float t[32][33];
    const int c0 = blockIdx.x * 32, r0 = blockIdx.y * 32;
    const int tx = threadIdx.x & 31, ty = threadIdx.x >> 5;  // 32 x 8
#pragma unroll
    for (int i = 0; i < 4; ++i)
        t[ty + 8 * i][tx] = in[(long long)(r0 + ty + 8 * i) * C + c0 + tx];
    __syncthreads();
#pragma unroll
    for (int i = 0; i < 4; ++i) {
        const long long o = (long long)(c0 + ty + 8 * i) * R + r0 + tx;
        oh[o] = __float2half(t[tx][ty + 8 * i]);
    }
}

// ---------------- softmax rows (2048) + fp16 hi write ----------------------
__global__ __launch_bounds__(256) void softmax_split_kernel(
    float* __restrict__ data, __half* __restrict__ wh, float scale)
{
    __shared__ float sred[256];
    const int tid = threadIdx.x;
    const long long rb = (long long)blockIdx.x * 2048;
    float* row = data + rb;

    float v[8];
    float m = -1e30f;
#pragma unroll
    for (int i = 0; i < 8; ++i) {
        v[i] = row[i * 256 + tid] * scale;
        m = fmaxf(m, v[i]);
    }
    sred[tid] = m;
    __syncthreads();
    for (int s = 128; s > 0; s >>= 1) {
        if (tid < s) sred[tid] = fmaxf(sred[tid], sred[tid + s]);
        __syncthreads();
    }
    m = sred[0];
    __syncthreads();

    float sum = 0.0f;
#pragma unroll
    for (int i = 0; i < 8; ++i) {
        v[i] = expf(v[i] - m);
        sum += v[i];
    }
    sred[tid] = sum;
    __syncthreads();
    for (int s = 128; s > 0; s >>= 1) {
        if (tid < s) sred[tid] += sred[tid + s];
        __syncthreads();
    }
    const float inv = 1.0f / sred[0];
#pragma unroll
    for (int i = 0; i < 8; ++i) {
        const float w = v[i] * inv;
        row[i * 256 + tid] = w;
        wh[rb + i * 256 + tid] = __float2half(w);
    }
}

// ---------------------------------------------------------------------------
extern "C" void kernel_launch(void* const* d_in, const int* in_sizes, int n_in,
                              void* d_out, int out_size)
{
    const float* Lt   = (const float*)d_in[0];   // [8, 2048, 1024]
    const float* rnn  = (const float*)d_in[1];   // [8, 2048, 1024]
    const float* kern = (const float*)d_in[2];   // [2, 1024, 1024]
    const float* W    = (const float*)d_in[3];   // [1024, 1024]

    float* ctx = (float*)d_out;                  // [8, 2048, 1024]
    float* wts = (float*)d_out + CTX_ELEMS;      // [8, 2048, 2048]

    __half *rnnh, *rnnl, *lth, *ltl, *wWh, *wWl, *k0h, *k0l, *k1th;
    __half *Ph, *Pl, *Th, *Tl, *wvth, *wh;
    cudaGetSymbolAddress((void**)&rnnh, g_rnn_h); cudaGetSymbolAddress((void**)&rnnl, g_rnn_l);
    cudaGetSymbolAddress((void**)&lth,  g_Lt_h);  cudaGetSymbolAddress((void**)&ltl,  g_Lt_l);
    cudaGetSymbolAddress((void**)&wWh,  g_W_h);   cudaGetSymbolAddress((void**)&wWl,  g_W_l);
    cudaGetSymbolAddress((void**)&k0h,  g_k0_h);  cudaGetSymbolAddress((void**)&k0l,  g_k0_l);
    cudaGetSymbolAddress((void**)&k1th, g_k1t_h);
    cudaGetSymbolAddress((void**)&Ph,   g_P_h);   cudaGetSymbolAddress((void**)&Pl,   g_P_l);
    cudaGetSymbolAddress((void**)&Th,   g_T_h);   cudaGetSymbolAddress((void**)&Tl,   g_T_l);
    cudaGetSymbolAddress((void**)&wvth, g_WVt_h);
    cudaGetSymbolAddress((void**)&wh,   g_w_h);

    const int SMEM3 = 2 * 4 * OP_BYTES;  // 81920
    const int SMEM1 = 2 * 2 * OP_BYTES;  // 40960
    cudaFuncSetAttribute(gemm_hmma<0,3>, cudaFuncAttributeMaxDynamicSharedMemorySize, SMEM3);
    cudaFuncSetAttribute(gemm_hmma<1,3>, cudaFuncAttributeMaxDynamicSharedMemorySize, SMEM3);
    cudaFuncSetAttribute(gemm_hmma<2,1>, cudaFuncAttributeMaxDynamicSharedMemorySize, SMEM1);
    cudaFuncSetAttribute(gemm_hmma<0,1>, cudaFuncAttributeMaxDynamicSharedMemorySize, SMEM1);

    // 0) fused splits + k1 transpose (hi only; WVt is x1 now)
    split_all_kernel<<<17408, 256>>>(rnn, Lt, W, kern,
                                     rnnh, rnnl, lth, ltl,
                                     wWh, wWl, k0h, k0l);
    splitT_kernel<<<dim3(32, 32, 1), 256>>>(kern + 1024 * 1024, k1th, 1024, 1024);

    // 2) P = k0 @ W^T  [1024,1024]  x3
    gemm_hmma<1,3><<<dim3(8, 8, 1), 256, SMEM3>>>(
        k0h, k0l, wWh, wWl, nullptr, Ph, Pl, 1024, 1024, 0, 0, 0);

    // 3) T = rnn @ P^T  [16384,1024]  x3
    gemm_hmma<1,3><<<dim3(8, 128, 1), 256, SMEM3>>>(
        rnnh, rnnl, Ph, Pl, nullptr, Th, Tl, 1024, 1024, 0, 0, 0);

    // 4) WVt = (Lt @ k1)^T per batch  x1 (EPI2: fused transpose, hi only)
    gemm_hmma<2,1><<<dim3(8, 128, 1), 256, SMEM1>>>(
        lth, nullptr, k1th, nullptr, nullptr, wvth, nullptr, 1024, 0, 0, 0, 0);

    // 5) QK = T @ Lt^T per batch  x3 -> fp32 wts slab of d_out
    gemm_hmma<0,3><<<dim3(16, 16, 8), 256, SMEM3>>>(
        Th, Tl, lth, ltl, wts, nullptr, nullptr, 1024, 2048,
        2048LL * 1024, 2048LL * 1024, 2048LL * 2048);

    // 6) softmax(QK * 0.125) in place + fp16 hi for context GEMM
    softmax_split_kernel<<<16384, 256>>>(wts, wh, 0.125f);

    // 7) ctx = weights @ WVt^T per batch, K=2048, x1
    gemm_hmma<0,1><<<dim3(8, 16, 8), 256, SMEM1>>>(
        wh, nullptr, wvth, nullptr, ctx, nullptr, nullptr, 2048, 1024,
        2048LL * 2048, 1024LL * 2048, 2048LL * 1024);
}

// round 12
// speedup vs baseline: 1.1787x; 1.0008x over previous
#include <cuda_runtime.h>
#include <cuda_fp16.h>
#include <stdint.h>

// ===========================================================================
// ScaledDotProductAttention R10: error-budgeted term counts per GEMM
//
//   P  = k0 @ W^T                    [1024,1024]  x3   (logit path)
//   T  = rnn @ P^T                   [16384,1024] x3   (logit path)
//   WVt= (Lt @ k1)^T per batch       [1024,2048]  x1   (post-softmax path)
//   QK = T @ Lt^T per batch          [2048,2048]  x3  -> fp32 (logit path)
//   weights = softmax(QK * 0.125)    -> d_out (+ fp16 hi for ctx)
//   ctx = weights @ WVt^T per batch  [2048,1024]  x1 -> d_out
//
// x3 = Ah*Bh (fp32 acc) + [Ah*Bl + Al*Bh] (shared fp16 acc, added at epi).
// ===========================================================================

#define NB 8
static const long long CTX_ELEMS = 8LL * 2048 * 1024;  // 16,777,216

// ---------------- device scratch (allocation-free rule) --------------------
#define NME (8 * 2048 * 1024)
__device__ __align__(128) __half g_rnn_h[NME], g_rnn_l[NME];
__device__ __align__(128) __half g_Lt_h[NME],  g_Lt_l[NME];
__device__ __align__(128) __half g_W_h[1024*1024],   g_W_l[1024*1024];
__device__ __align__(128) __half g_k0_h[1024*1024],  g_k0_l[1024*1024];
__device__ __align__(128) __half g_k1t_h[1024*1024], g_k1t_l[1024*1024];
__device__ __align__(128) __half g_P_h[1024*1024],   g_P_l[1024*1024];
__device__ __align__(128) __half g_T_h[NME], g_T_l[NME];
__device__ __align__(128) __half g_WVt_h[NME];
__device__ __align__(128) __half g_w_h[8LL*2048*2048];

// ---------------- helpers --------------------------------------------------
__device__ __forceinline__ uint32_t smem_u32(const void* p) {
    uint32_t a;
    asm("{ .reg .u64 t; cvta.to.shared.u64 t, %1; cvt.u32.u64 %0, t; }"
        : "=r"(a) : "l"(p));
    return a;
}
__device__ __forceinline__ void ldm4(uint32_t (&r)[4], uint32_t a) {
    asm volatile("ldmatrix.sync.aligned.m8n8.x4.shared.b16 {%0,%1,%2,%3}, [%4];"
        : "=r"(r[0]), "=r"(r[1]), "=r"(r[2]), "=r"(r[3]) : "r"(a));
}
// fp32-accumulate MMA
__device__ __forceinline__ void mma16816(float* c, const uint32_t* a,
                                         uint32_t b0, uint32_t b1) {
    asm volatile("mma.sync.aligned.m16n8k16.row.col.f32.f16.f16.f32 "
        "{%0,%1,%2,%3}, {%4,%5,%6,%7}, {%8,%9}, {%0,%1,%2,%3};"
        : "+f"(c[0]), "+f"(c[1]), "+f"(c[2]), "+f"(c[3])
        : "r"(a[0]), "r"(a[1]), "r"(a[2]), "r"(a[3]), "r"(b0), "r"(b1));
}
// fp16-accumulate MMA (cross terms; small relative magnitude)
__device__ __forceinline__ void mma16816h(uint32_t* c, const uint32_t* a,
                                          uint32_t b0, uint32_t b1) {
    asm volatile("mma.sync.aligned.m16n8k16.row.col.f16.f16.f16.f16 "
        "{%0,%1}, {%2,%3,%4,%5}, {%6,%7}, {%0,%1};"
        : "+r"(c[0]), "+r"(c[1])
        : "r"(a[0]), "r"(a[1]), "r"(a[2]), "r"(a[3]), "r"(b0), "r"(b1));
}
__device__ __forceinline__ void cpasync16(uint32_t s, const void* g) {
    asm volatile("cp.async.cg.shared.global [%0], [%1], 16;" :: "r"(s), "l"(g));
}

// ---------------- fp16 HMMA GEMM (NT=3: hi/lo split, NT=1: plain) ----------
// C[M,N] = A[M,K] @ B[N,K]^T, both K-major. CTA tile 128x128, 8 warps
// (warp tile 32x64), K-tile 32, 2-stage cp.async double buffer.
#define OP_BYTES 10240

// EPI 0: fp32 C.  EPI 1: fp16 hi/lo (Ch, Cl).
// EPI 2: transposed fp16 per batch of 2048 rows: out[e, s] (ld 2048);
//        writes hi+lo when NT==3, hi only when NT==1.
template <int EPI, int NT>
__global__ __launch_bounds__(256, 2) void gemm_hmma(
    const __half* __restrict__ Ah, const __half* __restrict__ Al,
    const __half* __restrict__ Bh, const __half* __restrict__ Bl,
    float* __restrict__ C, __half* __restrict__ Ch, __half* __restrict__ Cl,
    int K, int ldc, long long sA, long long sB, long long sC)
{
    constexpr int NOPS = (NT == 1) ? 2 : 4;
    constexpr uint32_t STAGE = NOPS * OP_BYTES;
    extern __shared__ char smem[];
    const uint32_t sbase = smem_u32(smem);
    const int tid  = threadIdx.x;
    const int lane = tid & 31, wid = tid >> 5;
    const int wm = wid & 3, wn = wid >> 2;   // warp grid 4(m) x 2(n)
    const long long bz = blockIdx.z;
    Ah += bz * sA; Bh += bz * sB;
    if (NT == 3) { Al += bz * sA; Bl += bz * sB; }
    const int row0 = blockIdx.y * 128;
    const int col0 = blockIdx.x * 128;

    float acch[2][8][4];           // hi*hi, fp32 accum
    uint32_t accx[2][8][2];        // cross terms, fp16 accum (half2 pairs)
#pragma unroll
    for (int i = 0; i < 2; ++i)
#pragma unroll
        for (int j = 0; j < 8; ++j) {
#pragma unroll
            for (int q = 0; q < 4; ++q) acch[i][j][q] = 0.0f;
            accx[i][j][0] = 0u; accx[i][j][1] = 0u;
        }

    auto load_stage = [&](int st, int k0) {
        const uint32_t base = sbase + st * STAGE;
#pragma unroll
        for (int j = 0; j < 2 * NOPS; ++j) {
            const int op  = j >> 1;                 // NT3: Ah,Al,Bh,Bl  NT1: Ah,Bh
            const int idx = ((j & 1) << 8) + tid;   // 0..511
            const int r = idx >> 2, c = idx & 3;    // row 0..127, 16B chunk
            const __half* gp;
            bool isA;
            if (NT == 1) { isA = (op == 0); gp = isA ? Ah : Bh; }
            else {
                isA = (op < 2);
                gp = (op == 0) ? Ah : (op == 1) ? Al : (op == 2) ? Bh : Bl;
            }
            const int gr = (isA ? row0 : col0) + r;
            cpasync16(base + op * OP_BYTES + r * 80 + c * 16,
                      gp + (long long)gr * K + k0 + c * 8);
        }
        asm volatile("cp.async.commit_group;");
    };

    const int ntiles = K >> 5;
    load_stage(0, 0);

    for (int kt = 0; kt < ntiles; ++kt) {
        asm volatile("cp.async.wait_group 0;" ::: "memory");
        __syncthreads();   // math(kt-1) done everywhere AND stage kt visible
        if (kt + 1 < ntiles)
            load_stage((kt + 1) & 1, (kt + 1) << 5);  // overwrites stage kt-1: safe

        const uint32_t st = sbase + (kt & 1) * STAGE;
        const uint32_t sAh = st;
        const uint32_t sAl = st + OP_BYTES;                       // NT3 only
        const uint32_t sBh = st + (NT == 1 ? 1 : 2) * OP_BYTES;
        const uint32_t sBl = st + 3 * OP_BYTES;                   // NT3 only
        const uint32_t lrow = (lane & 15) * 80 + (lane >> 4) * 16;

#pragma unroll
        for (int ks = 0; ks < 2; ++ks) {
            uint32_t afh[2][4], afl[2][4];
#pragma unroll
            for (int mt = 0; mt < 2; ++mt) {
                const uint32_t ao = (uint32_t)(wm * 32 + mt * 16) * 80 + ks * 32 + lrow;
                ldm4(afh[mt], sAh + ao);
                if (NT == 3) ldm4(afl[mt], sAl + ao);
            }
#pragma unroll
            for (int p = 0; p < 4; ++p) {
                uint32_t bfh[4], bfl[4];
                const uint32_t bo = (uint32_t)(wn * 64 + p * 16) * 80 + ks * 32 + lrow;
                ldm4(bfh, sBh + bo);
                if (NT == 3) ldm4(bfl, sBl + bo);
                // main term: fp32 accumulate
#pragma unroll
                for (int mt = 0; mt < 2; ++mt) {
                    mma16816(acch[mt][2*p],   afh[mt], bfh[0], bfh[2]);
                    mma16816(acch[mt][2*p+1], afh[mt], bfh[1], bfh[3]);
                }
                if (NT == 3) {
                    // cross terms: fp16 accumulate
#pragma unroll
                    for (int mt = 0; mt < 2; ++mt) {
                        mma16816h(accx[mt][2*p],   afh[mt], bfl[0], bfl[2]);
                        mma16816h(accx[mt][2*p+1], afh[mt], bfl[1], bfl[3]);
                    }
#pragma unroll
                    for (int mt = 0; mt < 2; ++mt) {
                        mma16816h(accx[mt][2*p],   afl[mt], bfh[0], bfh[2]);
                        mma16816h(accx[mt][2*p+1], afl[mt], bfh[1], bfh[3]);
                    }
                }
            }
        }
    }
    __syncthreads();

    // fold fp16 cross accumulators into the fp32 result
    if (NT == 3) {
#pragma unroll
        for (int mt = 0; mt < 2; ++mt)
#pragma unroll
            for (int nt = 0; nt < 8; ++nt) {
                const __half2 x0 = *(const __half2*)&accx[mt][nt][0];
                const __half2 x1 = *(const __half2*)&accx[mt][nt][1];
                acch[mt][nt][0] += __half2float(x0.x);
                acch[mt][nt][1] += __half2float(x0.y);
                acch[mt][nt][2] += __half2float(x1.x);
                acch[mt][nt][3] += __half2float(x1.y);
            }
    }

    const int l4 = lane >> 2, l2 = (lane & 3) * 2;

    if (EPI == 2) {
        // Transposed epilogue: stage tile in smem, write out[e,s].
        constexpr int NPASS = (NT == 3) ? 2 : 1;   // hi (+ lo if split output)
        __half* sst = (__half*)smem;          // stride 130 halves per m-row
        const int b  = row0 >> 11;            // batch (2048 rows per batch)
        const int s0 = row0 & 2047;
        __half* outs[2] = {Ch, Cl};
#pragma unroll
        for (int pass = 0; pass < NPASS; ++pass) {
#pragma unroll
            for (int mt = 0; mt < 2; ++mt) {
#pragma unroll
                for (int nt = 0; nt < 8; ++nt) {
                    const int rl = wm * 32 + mt * 16 + l4;
                    const int cl = wn * 64 + nt * 8 + l2;
                    const float* a = acch[mt][nt];
                    __half2 v0, v1;
                    __half h0 = __float2half(a[0]), h1 = __float2half(a[1]);
                    __half h2 = __float2half(a[2]), h3 = __float2half(a[3]);
                    if (pass == 0) {
                        v0 = __halves2half2(h0, h1);
                        v1 = __halves2half2(h2, h3);
                    } else {
                        v0 = __halves2half2(__float2half(a[0] - __half2float(h0)),
                                            __float2half(a[1] - __half2float(h1)));
                        v1 = __halves2half2(__float2half(a[2] - __half2float(h2)),
                                            __float2half(a[3] - __half2float(h3)));
                    }
                    *(__half2*)&sst[rl * 130 + cl]       = v0;
                    *(__half2*)&sst[(rl + 8) * 130 + cl] = v1;
                }
            }
            __syncthreads();
            __half* op = outs[pass];
#pragma unroll
            for (int j = 0; j < 16; ++j) {
                const int e = j * 8 + wid;
                __half v[4];
#pragma unroll
                for (int q = 0; q < 4; ++q)
                    v[q] = sst[(4 * lane + q) * 130 + e];
                const long long o = (long long)b * (1024LL * 2048) +
                                    (long long)(col0 + e) * 2048 + s0 + 4 * lane;
                *(uint2*)(op + o) = *(uint2*)v;
            }
            __syncthreads();
        }
        return;
    }

#pragma unroll
    for (int mt = 0; mt < 2; ++mt) {
#pragma unroll
        for (int nt = 0; nt < 8; ++nt) {
            const int r  = row0 + wm * 32 + mt * 16 + l4;
            const int cc = col0 + wn * 64 + nt * 8 + l2;
            const long long o0 = bz * sC + (long long)r * ldc + cc;
            const long long o1 = o0 + 8LL * ldc;
            const float* a = acch[mt][nt];
            if (EPI == 0) {
                *(float2*)(C + o0) = make_float2(a[0], a[1]);
                *(float2*)(C + o1) = make_float2(a[2], a[3]);
            } else {
                __half2 hh, ll;
                hh.x = __float2half(a[0]); hh.y = __float2half(a[1]);
                ll.x = __float2half(a[0] - __half2float(hh.x));
                ll.y = __float2half(a[1] - __half2float(hh.y));
                *(__half2*)(Ch + o0) = hh;
                *(__half2*)(Cl + o0) = ll;
                hh.x = __float2half(a[2]); hh.y = __float2half(a[3]);
                ll.x = __float2half(a[2] - __half2float(hh.x));
                ll.y = __float2half(a[3] - __half2float(hh.y));
                *(__half2*)(Ch + o1) = hh;
                *(__half2*)(Cl + o1) = ll;
            }
        }
    }
}

// ---------------- fused fp32 -> hi/lo fp16 split for all 4 inputs ----------
// blocks [0,8192): rnn   [8192,16384): Lt   [16384,16896): W   [16896,17408): k0
__global__ __launch_bounds__(256) void split_all_kernel(
    const float* __restrict__ rnn, const float* __restrict__ Lt,
    const float* __restrict__ W,   const float* __restrict__ k0,
    __half* __restrict__ rnnh, __half* __restrict__ rnnl,
    __half* __restrict__ lth,  __half* __restrict__ ltl,
    __half* __restrict__ wh,   __half* __restrict__ wl,
    __half* __restrict__ k0h,  __half* __restrict__ k0l)
{
    const float* x; __half *h, *l;
    long long blk = blockIdx.x;
    if (blk < 8192)       { x = rnn; h = rnnh; l = rnnl; }
    else if (blk < 16384) { x = Lt;  h = lth;  l = ltl;  blk -= 8192; }
    else if (blk < 16896) { x = W;   h = wh;   l = wl;   blk -= 16384; }
    else                  { x = k0;  h = k0h;  l = k0l;  blk -= 16896; }

    const long long i0 = (blk * 256 + threadIdx.x) * 8;
#pragma unroll
    for (int v = 0; v < 2; ++v) {
        const float4 f = *(const float4*)(x + i0 + v * 4);
        const float ff[4] = {f.x, f.y, f.z, f.w};
        __half hh[4], ll[4];
#pragma unroll
        for (int j = 0; j < 4; ++j) {
            hh[j] = __float2half(ff[j]);
            ll[j] = __float2half(ff[j] - __half2float(hh[j]));
        }
        *(uint2*)(h + i0 + v * 4) = *(uint2*)hh;
        *(uint2*)(l + i0 + v * 4) = *(uint2*)ll;
    }
}

// ---------------- fp32 [R,C] -> transposed fp16 hi [C,R] -------------------
__global__ __launch_bounds__(256) void splitT_kernel(
    const float* __restrict__ in, __half* __restrict__ oh, int R, int C)
{
    __shared__ float t[32][33];
    const int c0 = blockIdx.x * 32, r0 = blockIdx.y * 32;
    const int tx = threadIdx.x & 31, ty = threadIdx.x >> 5;  // 32 x 8
#pragma unroll
    for (int i = 0; i < 4; ++i)
        t[ty + 8 * i][tx] = in[(long long)(r0 + ty + 8 * i) * C + c0 + tx];
    __syncthreads();
#pragma unroll
    for (int i = 0; i < 4; ++i) {
        const long long o = (long long)(c0 + ty + 8 * i) * R + r0 + tx;
        oh[o] = __float2half(t[tx][ty + 8 * i]);
    }
}

// ---------------- softmax rows (2048) + fp16 hi write ----------------------
__global__ __launch_bounds__(256) void softmax_split_kernel(
    float* __restrict__ data, __half* __restrict__ wh, float scale)
{
    __shared__ float sred[256];
    const int tid = threadIdx.x;
    const long long rb = (long long)blockIdx.x * 2048;
    float* row = data + rb;

    float v[8];
    float m = -1e30f;
#pragma unroll
    for (int i = 0; i < 8; ++i) {
        v[i] = row[i * 256 + tid] * scale;
        m = fmaxf(m, v[i]);
    }
    sred[tid] = m;
    __syncthreads();
    for (int s = 128; s > 0; s >>= 1) {
        if (tid < s) sred[tid] = fmaxf(sred[tid], sred[tid + s]);
        __syncthreads();
    }
    m = sred[0];
    __syncthreads();

    float sum = 0.0f;
#pragma unroll
    for (int i = 0; i < 8; ++i) {
        v[i] = expf(v[i] - m);
        sum += v[i];
    }
    sred[tid] = sum;
    __syncthreads();
    for (int s = 128; s > 0; s >>= 1) {
        if (tid < s) sred[tid] += sred[tid + s];
        __syncthreads();
    }
    const float inv = 1.0f / sred[0];
#pragma unroll
    for (int i = 0; i < 8; ++i) {
        const float w = v[i] * inv;
        row[i * 256 + tid] = w;
        wh[rb + i * 256 + tid] = __float2half(w);
    }
}

// ---------------------------------------------------------------------------
extern "C" void kernel_launch(void* const* d_in, const int* in_sizes, int n_in,
                              void* d_out, int out_size)
{
    const float* Lt   = (const float*)d_in[0];   // [8, 2048, 1024]
    const float* rnn  = (const float*)d_in[1];   // [8, 2048, 1024]
    const float* kern = (const float*)d_in[2];   // [2, 1024, 1024]
    const float* W    = (const float*)d_in[3];   // [1024, 1024]

    float* ctx = (float*)d_out;                  // [8, 2048, 1024]
    float* wts = (float*)d_out + CTX_ELEMS;      // [8, 2048, 2048]

    __half *rnnh, *rnnl, *lth, *ltl, *wWh, *wWl, *k0h, *k0l, *k1th;
    __half *Ph, *Pl, *Th, *Tl, *wvth, *wh;
    cudaGetSymbolAddress((void**)&rnnh, g_rnn_h); cudaGetSymbolAddress((void**)&rnnl, g_rnn_l);
    cudaGetSymbolAddress((void**)&lth,  g_Lt_h);  cudaGetSymbolAddress((void**)&ltl,  g_Lt_l);
    cudaGetSymbolAddress((void**)&wWh,  g_W_h);   cudaGetSymbolAddress((void**)&wWl,  g_W_l);
    cudaGetSymbolAddress((void**)&k0h,  g_k0_h);  cudaGetSymbolAddress((void**)&k0l,  g_k0_l);
    cudaGetSymbolAddress((void**)&k1th, g_k1t_h);
    cudaGetSymbolAddress((void**)&Ph,   g_P_h);   cudaGetSymbolAddress((void**)&Pl,   g_P_l);
    cudaGetSymbolAddress((void**)&Th,   g_T_h);   cudaGetSymbolAddress((void**)&Tl,   g_T_l);
    cudaGetSymbolAddress((void**)&wvth, g_WVt_h);
    cudaGetSymbolAddress((void**)&wh,   g_w_h);

    const int SMEM3 = 2 * 4 * OP_BYTES;  // 81920
    const int SMEM1 = 2 * 2 * OP_BYTES;  // 40960
    cudaFuncSetAttribute(gemm_hmma<0,3>, cudaFuncAttributeMaxDynamicSharedMemorySize, SMEM3);
    cudaFuncSetAttribute(gemm_hmma<1,3>, cudaFuncAttributeMaxDynamicSharedMemorySize, SMEM3);
    cudaFuncSetAttribute(gemm_hmma<2,1>, cudaFuncAttributeMaxDynamicSharedMemorySize, SMEM1);
    cudaFuncSetAttribute(gemm_hmma<0,1>, cudaFuncAttributeMaxDynamicSharedMemorySize, SMEM1);

    // 0) fused splits + k1 transpose (hi only; WVt is x1 now)
    split_all_kernel<<<17408, 256>>>(rnn, Lt, W, kern,
                                     rnnh, rnnl, lth, ltl,
                                     wWh, wWl, k0h, k0l);
    splitT_kernel<<<dim3(32, 32, 1), 256>>>(kern + 1024 * 1024, k1th, 1024, 1024);

    // 2) P = k0 @ W^T  [1024,1024]  x3
    gemm_hmma<1,3><<<dim3(8, 8, 1), 256, SMEM3>>>(
        k0h, k0l, wWh, wWl, nullptr, Ph, Pl, 1024, 1024, 0, 0, 0);

    // 3) T = rnn @ P^T  [16384,1024]  x3
    gemm_hmma<1,3><<<dim3(8, 128, 1), 256, SMEM3>>>(
        rnnh, rnnl, Ph, Pl, nullptr, Th, Tl, 1024, 1024, 0, 0, 0);

    // 4) WVt = (Lt @ k1)^T per batch  x1 (EPI2: fused transpose, hi only)
    gemm_hmma<2,1><<<dim3(8, 128, 1), 256, SMEM1>>>(
        lth, nullptr, k1th, nullptr, nullptr, wvth, nullptr, 1024, 0, 0, 0, 0);

    // 5) QK = T @ Lt^T per batch  x3 -> fp32 wts slab of d_out
    gemm_hmma<0,3><<<dim3(16, 16, 8), 256, SMEM3>>>(
        Th, Tl, lth, ltl, wts, nullptr, nullptr, 1024, 2048,
        2048LL * 1024, 2048LL * 1024, 2048LL * 2048);

    // 6) softmax(QK * 0.125) in place + fp16 hi for context GEMM
    softmax_split_kernel<<<16384, 256>>>(wts, wh, 0.125f);

    // 7) ctx = weights @ WVt^T per batch, K=2048, x1
    gemm_hmma<0,1><<<dim3(8, 16, 8), 256, SMEM1>>>(
        wh, nullptr, wvth, nullptr, ctx, nullptr, nullptr, 2048, 1024,
        2048LL * 2048, 1024LL * 2048, 2048LL * 1024);
}

// round 14
// speedup vs baseline: 1.3188x; 1.1188x over previous
#include <cuda_runtime.h>
#include <cuda_fp16.h>
#include <stdint.h>

// ===========================================================================
// ScaledDotProductAttention R14 (= R13 resubmit after infra failure):
// all GEMMs plain fp16 via scaled-residual x2
//
// Planes per operand X: Xh = fl16(x), Xm = fl16(32x - 31*Xh)  ("merged")
// Then X@Y = (31/32)*(Xh@Yh) + (1/32)*(Xm@Ym) + O(4e-5) relative.
//
//   P  = k0 @ W^T        : P_S, P_M(combine -> Ph,Pm)      [1024,1024]
//   T  = rnn @ P^T       : T_S, T_M(combine -> Th,Tm)      [16384,1024]
//   WVt= (Lt @ k1)^T     : x1 hi-only, fused transpose     [1024,2048]/batch
//   QK = T @ Lt^T        : QK_S -> wts, QK_M combine in place (fp32 logits)
//   weights = softmax(QK * 0.125)  -> d_out (+ fp16 hi for ctx)
//   ctx = weights @ WVt^T per batch -> d_out
// ===========================================================================

#define NB 8
static const long long CTX_ELEMS = 8LL * 2048 * 1024;  // 16,777,216

// ---------------- device scratch (allocation-free rule) --------------------
#define NME (8 * 2048 * 1024)
__device__ __align__(128) __half g_rnn_h[NME], g_rnn_m[NME];
__device__ __align__(128) __half g_Lt_h[NME],  g_Lt_m[NME];
__device__ __align__(128) __half g_W_h[1024*1024],  g_W_m[1024*1024];
__device__ __align__(128) __half g_k0_h[1024*1024], g_k0_m[1024*1024];
__device__ __align__(128) __half g_k1t_h[1024*1024];
__device__ __align__(128) __half g_P_h[1024*1024],  g_P_m[1024*1024];
__device__ __align__(128) float  g_PS[1024*1024];
__device__ __align__(128) __half g_T_h[NME], g_T_m[NME];
__device__ __align__(128) float  g_TS[NME];
__device__ __align__(128) __half g_WVt_h[NME];
__device__ __align__(128) __half g_w_h[8LL*2048*2048];

// ---------------- helpers --------------------------------------------------
__device__ __forceinline__ uint32_t smem_u32(const void* p) {
    uint32_t a;
    asm("{ .reg .u64 t; cvta.to.shared.u64 t, %1; cvt.u32.u64 %0, t; }"
        : "=r"(a) : "l"(p));
    return a;
}
__device__ __forceinline__ void ldm4(uint32_t (&r)[4], uint32_t a) {
    asm volatile("ldmatrix.sync.aligned.m8n8.x4.shared.b16 {%0,%1,%2,%3}, [%4];"
        : "=r"(r[0]), "=r"(r[1]), "=r"(r[2]), "=r"(r[3]) : "r"(a));
}
__device__ __forceinline__ void mma16816(float* c, const uint32_t* a,
                                         uint32_t b0, uint32_t b1) {
    asm volatile("mma.sync.aligned.m16n8k16.row.col.f32.f16.f16.f32 "
        "{%0,%1,%2,%3}, {%4,%5,%6,%7}, {%8,%9}, {%0,%1,%2,%3};"
        : "+f"(c[0]), "+f"(c[1]), "+f"(c[2]), "+f"(c[3])
        : "r"(a[0]), "r"(a[1]), "r"(a[2]), "r"(a[3]), "r"(b0), "r"(b1));
}
__device__ __forceinline__ void cpasync16(uint32_t s, const void* g) {
    asm volatile("cp.async.cg.shared.global [%0], [%1], 16;" :: "r"(s), "l"(g));
}
// merged-plane helper: m = fl16(32x - 31*h)
__device__ __forceinline__ __half mk_m(float x, __half h) {
    return __float2half(32.0f * x - 31.0f * __half2float(h));
}

// ---------------- plain fp16 HMMA GEMM -------------------------------------
// C[M,N] = A[M,K] @ B[N,K]^T, both K-major. CTA tile 128x128, 8 warps
// (warp tile 32x64), K-tile 32, 2-stage cp.async double buffer.
// EPI 0: store fp32 C.
// EPI 2: transposed fp16 hi per batch of 2048 rows: Ch[e, s] (ld 2048).
// EPI 3: combine with fp32 S (read via C): t = (31/32)S + acc/32;
//        write Ch = fl16(t), Cl = fl16(32t - 31*Ch).
// EPI 4: combine in place: C = (31/32)C + acc/32 (fp32).
#define OP_BYTES 10240

template <int EPI>
__global__ __launch_bounds__(256, 2) void gemm_hmma(
    const __half* __restrict__ A, const __half* __restrict__ B,
    float* __restrict__ C, __half* __restrict__ Ch, __half* __restrict__ Cl,
    int K, int ldc, long long sA, long long sB, long long sC)
{
    constexpr uint32_t STAGE = 2 * OP_BYTES;   // A, B
    extern __shared__ char smem[];
    const uint32_t sbase = smem_u32(smem);
    const int tid  = threadIdx.x;
    const int lane = tid & 31, wid = tid >> 5;
    const int wm = wid & 3, wn = wid >> 2;   // warp grid 4(m) x 2(n)
    const long long bz = blockIdx.z;
    A += bz * sA; B += bz * sB;
    const int row0 = blockIdx.y * 128;
    const int col0 = blockIdx.x * 128;

    float acc[2][8][4];
#pragma unroll
    for (int i = 0; i < 2; ++i)
#pragma unroll
        for (int j = 0; j < 8; ++j)
#pragma unroll
            for (int q = 0; q < 4; ++q) acc[i][j][q] = 0.0f;

    auto load_stage = [&](int st, int k0) {
        const uint32_t base = sbase + st * STAGE;
#pragma unroll
        for (int j = 0; j < 4; ++j) {
            const int op  = j >> 1;                 // 0:A 1:B
            const int idx = ((j & 1) << 8) + tid;   // 0..511
            const int r = idx >> 2, c = idx & 3;    // row 0..127, 16B chunk
            const __half* gp = (op == 0) ? A : B;
            const int gr = ((op == 0) ? row0 : col0) + r;
            cpasync16(base + op * OP_BYTES + r * 80 + c * 16,
                      gp + (long long)gr * K + k0 + c * 8);
        }
        asm volatile("cp.async.commit_group;");
    };

    const int ntiles = K >> 5;
    load_stage(0, 0);

    for (int kt = 0; kt < ntiles; ++kt) {
        asm volatile("cp.async.wait_group 0;" ::: "memory");
        __syncthreads();   // math(kt-1) done everywhere AND stage kt visible
        if (kt + 1 < ntiles)
            load_stage((kt + 1) & 1, (kt + 1) << 5);  // overwrites kt-1: safe

        const uint32_t st  = sbase + (kt & 1) * STAGE;
        const uint32_t sA_ = st, sB_ = st + OP_BYTES;
        const uint32_t lrow = (lane & 15) * 80 + (lane >> 4) * 16;

#pragma unroll
        for (int ks = 0; ks < 2; ++ks) {
            uint32_t af[2][4];
#pragma unroll
            for (int mt = 0; mt < 2; ++mt)
                ldm4(af[mt], sA_ + (uint32_t)(wm * 32 + mt * 16) * 80 + ks * 32 + lrow);
#pragma unroll
            for (int p = 0; p < 4; ++p) {
                uint32_t bf[4];
                ldm4(bf, sB_ + (uint32_t)(wn * 64 + p * 16) * 80 + ks * 32 + lrow);
#pragma unroll
                for (int mt = 0; mt < 2; ++mt) {
                    mma16816(acc[mt][2*p],   af[mt], bf[0], bf[2]);
                    mma16816(acc[mt][2*p+1], af[mt], bf[1], bf[3]);
                }
            }
        }
    }
    __syncthreads();

    const int l4 = lane >> 2, l2 = (lane & 3) * 2;

    if (EPI == 2) {
        // Transposed hi-only epilogue: stage tile in smem, write Ch[e, s].
        __half* sst = (__half*)smem;          // stride 130 halves per m-row
        const int b  = row0 >> 11;            // batch (2048 rows per batch)
        const int s0 = row0 & 2047;
#pragma unroll
        for (int mt = 0; mt < 2; ++mt)
#pragma unroll
            for (int nt = 0; nt < 8; ++nt) {
                const int rl = wm * 32 + mt * 16 + l4;
                const int cl = wn * 64 + nt * 8 + l2;
                const float* a = acc[mt][nt];
                *(__half2*)&sst[rl * 130 + cl] =
                    __halves2half2(__float2half(a[0]), __float2half(a[1]));
                *(__half2*)&sst[(rl + 8) * 130 + cl] =
                    __halves2half2(__float2half(a[2]), __float2half(a[3]));
            }
        __syncthreads();
#pragma unroll
        for (int j = 0; j < 16; ++j) {
            const int e = j * 8 + wid;
            __half v[4];
#pragma unroll
            for (int q = 0; q < 4; ++q)
                v[q] = sst[(4 * lane + q) * 130 + e];
            const long long o = (long long)b * (1024LL * 2048) +
                                (long long)(col0 + e) * 2048 + s0 + 4 * lane;
            *(uint2*)(Ch + o) = *(uint2*)v;
        }
        return;
    }

#pragma unroll
    for (int mt = 0; mt < 2; ++mt) {
#pragma unroll
        for (int nt = 0; nt < 8; ++nt) {
            const int r  = row0 + wm * 32 + mt * 16 + l4;
            const int cc = col0 + wn * 64 + nt * 8 + l2;
            const long long o0 = bz * sC + (long long)r * ldc + cc;
            const long long o1 = o0 + 8LL * ldc;
            const float* a = acc[mt][nt];
            if (EPI == 0) {
                *(float2*)(C + o0) = make_float2(a[0], a[1]);
                *(float2*)(C + o1) = make_float2(a[2], a[3]);
            } else if (EPI == 4) {
                float2 s0v = *(float2*)(C + o0);
                float2 s1v = *(float2*)(C + o1);
                *(float2*)(C + o0) = make_float2(
                    0.96875f * s0v.x + 0.03125f * a[0],
                    0.96875f * s0v.y + 0.03125f * a[1]);
                *(float2*)(C + o1) = make_float2(
                    0.96875f * s1v.x + 0.03125f * a[2],
                    0.96875f * s1v.y + 0.03125f * a[3]);
            } else {  // EPI == 3: combine + emit (h, m) planes
                const float2 s0v = *(const float2*)(C + o0);
                const float2 s1v = *(const float2*)(C + o1);
                const float t0 = 0.96875f * s0v.x + 0.03125f * a[0];
                const float t1 = 0.96875f * s0v.y + 0.03125f * a[1];
                const float t2 = 0.96875f * s1v.x + 0.03125f * a[2];
                const float t3 = 0.96875f * s1v.y + 0.03125f * a[3];
                const __half h0 = __float2half(t0), h1 = __float2half(t1);
                const __half h2 = __float2half(t2), h3 = __float2half(t3);
                *(__half2*)(Ch + o0) = __halves2half2(h0, h1);
                *(__half2*)(Ch + o1) = __halves2half2(h2, h3);
                *(__half2*)(Cl + o0) = __halves2half2(mk_m(t0, h0), mk_m(t1, h1));
                *(__half2*)(Cl + o1) = __halves2half2(mk_m(t2, h2), mk_m(t3, h3));
            }
        }
    }
}

// ---------------- fused fp32 -> (h, m) planes for all 4 inputs -------------
// blocks [0,8192): rnn   [8192,16384): Lt   [16384,16896): W   [16896,17408): k0
__global__ __launch_bounds__(256) void split_all_kernel(
    const float* __restrict__ rnn, const float* __restrict__ Lt,
    const float* __restrict__ W,   const float* __restrict__ k0,
    __half* __restrict__ rnnh, __half* __restrict__ rnnm,
    __half* __restrict__ lth,  __half* __restrict__ ltm,
    __half* __restrict__ wh,   __half* __restrict__ wm,
    __half* __restrict__ k0h,  __half* __restrict__ k0m)
{
    const float* x; __half *h, *m;
    long long blk = blockIdx.x;
    if (blk < 8192)       { x = rnn; h = rnnh; m = rnnm; }
    else if (blk < 16384) { x = Lt;  h = lth;  m = ltm;  blk -= 8192; }
    else if (blk < 16896) { x = W;   h = wh;   m = wm;   blk -= 16384; }
    else                  { x = k0;  h = k0h;  m = k0m;  blk -= 16896; }

    const long long i0 = (blk * 256 + threadIdx.x) * 8;
#pragma unroll
    for (int v = 0; v < 2; ++v) {
        const float4 f = *(const float4*)(x + i0 + v * 4);
        const float ff[4] = {f.x, f.y, f.z, f.w};
        __half hh[4], mm[4];
#pragma unroll
        for (int j = 0; j < 4; ++j) {
            hh[j] = __float2half(ff[j]);
            mm[j] = mk_m(ff[j], hh[j]);
        }
        *(uint2*)(h + i0 + v * 4) = *(uint2*)hh;
        *(uint2*)(m + i0 + v * 4) = *(uint2*)mm;
    }
}

// ---------------- fp32 [R,C] -> transposed fp16 hi [C,R] -------------------
__global__ __launch_bounds__(256) void splitT_kernel(
    const float* __restrict__ in, __half* __restrict__ oh, int R, int C)
{
    __shared__ float t[32][33];
    const int c0 = blockIdx.x * 32, r0 = blockIdx.y * 32;
    const int tx = threadIdx.x & 31, ty = threadIdx.x >> 5;  // 32 x 8
#pragma unroll
    for (int i = 0; i < 4; ++i)
        t[ty + 8 * i][tx] = in[(long long)(r0 + ty + 8 * i) * C + c0 + tx];
    __syncthreads();
#pragma unroll
    for (int i = 0; i < 4; ++i) {
        const long long o = (long long)(c0 + ty + 8 * i) * R + r0 + tx;
        oh[o] = __float2half(t[tx][ty + 8 * i]);
    }
}

// ---------------- softmax rows (2048) + fp16 hi write ----------------------
__global__ __launch_bounds__(256) void softmax_split_kernel(
    float* __restrict__ data, __half* __restrict__ wh, float scale)
{
    __shared__ float sred[256];
    const int tid = threadIdx.x;
    const long long rb = (long long)blockIdx.x * 2048;
    float* row = data + rb;

    float v[8];
    float m = -1e30f;
#pragma unroll
    for (int i = 0; i < 8; ++i) {
        v[i] = row[i * 256 + tid] * scale;
        m = fmaxf(m, v[i]);
    }
    sred[tid] = m;
    __syncthreads();
    for (int s = 128; s > 0; s >>= 1) {
        if (tid < s) sred[tid] = fmaxf(sred[tid], sred[tid + s]);
        __syncthreads();
    }
    m = sred[0];
    __syncthreads();

    float sum = 0.0f;
#pragma unroll
    for (int i = 0; i < 8; ++i) {
        v[i] = expf(v[i] - m);
        sum += v[i];
    }
    sred[tid] = sum;
    __syncthreads();
    for (int s = 128; s > 0; s >>= 1) {
        if (tid < s) sred[tid] += sred[tid + s];
        __syncthreads();
    }
    const float inv = 1.0f / sred[0];
#pragma unroll
    for (int i = 0; i < 8; ++i) {
        const float w = v[i] * inv;
        row[i * 256 + tid] = w;
        wh[rb + i * 256 + tid] = __float2half(w);
    }
}

// ---------------------------------------------------------------------------
extern "C" void kernel_launch(void* const* d_in, const int* in_sizes, int n_in,
                              void* d_out, int out_size)
{
    const float* Lt   = (const float*)d_in[0];   // [8, 2048, 1024]
    const float* rnn  = (const float*)d_in[1];   // [8, 2048, 1024]
    const float* kern = (const float*)d_in[2];   // [2, 1024, 1024]
    const float* W    = (const float*)d_in[3];   // [1024, 1024]

    float* ctx = (float*)d_out;                  // [8, 2048, 1024]
    float* wts = (float*)d_out + CTX_ELEMS;      // [8, 2048, 2048]

    __half *rnnh, *rnnm, *lth, *ltm, *wWh, *wWm, *k0h, *k0m, *k1th;
    __half *Ph, *Pm, *Th, *Tm, *wvth, *wh;
    float *PS, *TS;
    cudaGetSymbolAddress((void**)&rnnh, g_rnn_h); cudaGetSymbolAddress((void**)&rnnm, g_rnn_m);
    cudaGetSymbolAddress((void**)&lth,  g_Lt_h);  cudaGetSymbolAddress((void**)&ltm,  g_Lt_m);
    cudaGetSymbolAddress((void**)&wWh,  g_W_h);   cudaGetSymbolAddress((void**)&wWm,  g_W_m);
    cudaGetSymbolAddress((void**)&k0h,  g_k0_h);  cudaGetSymbolAddress((void**)&k0m,  g_k0_m);
    cudaGetSymbolAddress((void**)&k1th, g_k1t_h);
    cudaGetSymbolAddress((void**)&Ph,   g_P_h);   cudaGetSymbolAddress((void**)&Pm,   g_P_m);
    cudaGetSymbolAddress((void**)&PS,   g_PS);
    cudaGetSymbolAddress((void**)&Th,   g_T_h);   cudaGetSymbolAddress((void**)&Tm,   g_T_m);
    cudaGetSymbolAddress((void**)&TS,   g_TS);
    cudaGetSymbolAddress((void**)&wvth, g_WVt_h);
    cudaGetSymbolAddress((void**)&wh,   g_w_h);

    const int SMEM = 2 * 2 * OP_BYTES;  // 40960
    cudaFuncSetAttribute(gemm_hmma<0>, cudaFuncAttributeMaxDynamicSharedMemorySize, SMEM);
    cudaFuncSetAttribute(gemm_hmma<2>, cudaFuncAttributeMaxDynamicSharedMemorySize, SMEM);
    cudaFuncSetAttribute(gemm_hmma<3>, cudaFuncAttributeMaxDynamicSharedMemorySize, SMEM);
    cudaFuncSetAttribute(gemm_hmma<4>, cudaFuncAttributeMaxDynamicSharedMemorySize, SMEM);

    // 0) (h, m) planes for rnn/Lt/W/k0 + k1 transpose (hi only)
    split_all_kernel<<<17408, 256>>>(rnn, Lt, W, kern,
                                     rnnh, rnnm, lth, ltm,
                                     wWh, wWm, k0h, k0m);
    splitT_kernel<<<dim3(32, 32, 1), 256>>>(kern + 1024 * 1024, k1th, 1024, 1024);

    // 1) P = k0 @ W^T : S pass then M pass (combine -> Ph, Pm)
    gemm_hmma<0><<<dim3(8, 8, 1), 256, SMEM>>>(
        k0h, wWh, PS, nullptr, nullptr, 1024, 1024, 0, 0, 0);
    gemm_hmma<3><<<dim3(8, 8, 1), 256, SMEM>>>(
        k0m, wWm, PS, Ph, Pm, 1024, 1024, 0, 0, 0);

    // 2) T = rnn @ P^T : S pass then M pass (combine -> Th, Tm)
    gemm_hmma<0><<<dim3(8, 128, 1), 256, SMEM>>>(
        rnnh, Ph, TS, nullptr, nullptr, 1024, 1024, 0, 0, 0);
    gemm_hmma<3><<<dim3(8, 128, 1), 256, SMEM>>>(
        rnnm, Pm, TS, Th, Tm, 1024, 1024, 0, 0, 0);

    // 3) WVt = (Lt @ k1)^T per batch (hi-only, fused transpose)
    gemm_hmma<2><<<dim3(8, 128, 1), 256, SMEM>>>(
        lth, k1th, nullptr, wvth, nullptr, 1024, 0, 0, 0, 0);

    // 4) QK: S pass -> wts (fp32), M pass combines in place
    gemm_hmma<0><<<dim3(16, 16, 8), 256, SMEM>>>(
        Th, lth, wts, nullptr, nullptr, 1024, 2048,
        2048LL * 1024, 2048LL * 1024, 2048LL * 2048);
    gemm_hmma<4><<<dim3(16, 16, 8), 256, SMEM>>>(
        Tm, ltm, wts, nullptr, nullptr, 1024, 2048,
        2048LL * 1024, 2048LL * 1024, 2048LL * 2048);

    // 5) softmax(QK * 0.125) in place + fp16 hi for context GEMM
    softmax_split_kernel<<<16384, 256>>>(wts, wh, 0.125f);

    // 6) ctx = weights @ WVt^T per batch, K=2048
    gemm_hmma<0><<<dim3(8, 16, 8), 256, SMEM>>>(
        wh, wvth, ctx, nullptr, nullptr, 2048, 1024,
        2048LL * 2048, 1024LL * 2048, 2048LL * 1024);
}

// round 17
// speedup vs baseline: 1.4581x; 1.1056x over previous
#include <cuda_runtime.h>
#include <cuda_fp16.h>
#include <stdint.h>

// ===========================================================================
// ScaledDotProductAttention R15: scaled-residual x2 + K-tile 64
//
// Planes per operand X: Xh = fl16(x), Xm = fl16(32x - 31*Xh)  ("merged")
// Then X@Y = (31/32)*(Xh@Yh) + (1/32)*(Xm@Ym) + O(4e-5) relative.
//
//   P  = k0 @ W^T        : P_S, P_M(combine -> Ph,Pm)      [1024,1024]
//   T  = rnn @ P^T       : T_S, T_M(combine -> Th,Tm)      [16384,1024]
//   WVt= (Lt @ k1)^T     : x1 hi-only, fused transpose     [1024,2048]/batch
//   QK = T @ Lt^T        : QK_S -> wts, QK_M combine in place (fp32 logits)
//   weights = softmax(QK * 0.125)  -> d_out (+ fp16 hi for ctx)
//   ctx = weights @ WVt^T per batch -> d_out
// ===========================================================================

#define NB 8
static const long long CTX_ELEMS = 8LL * 2048 * 1024;  // 16,777,216

// ---------------- device scratch (allocation-free rule) --------------------
#define NME (8 * 2048 * 1024)
__device__ __align__(128) __half g_rnn_h[NME], g_rnn_m[NME];
__device__ __align__(128) __half g_Lt_h[NME],  g_Lt_m[NME];
__device__ __align__(128) __half g_W_h[1024*1024],  g_W_m[1024*1024];
__device__ __align__(128) __half g_k0_h[1024*1024], g_k0_m[1024*1024];
__device__ __align__(128) __half g_k1t_h[1024*1024];
__device__ __align__(128) __half g_P_h[1024*1024],  g_P_m[1024*1024];
__device__ __align__(128) float  g_PS[1024*1024];
__device__ __align__(128) __half g_T_h[NME], g_T_m[NME];
__device__ __align__(128) float  g_TS[NME];
__device__ __align__(128) __half g_WVt_h[NME];
__device__ __align__(128) __half g_w_h[8LL*2048*2048];

// ---------------- helpers --------------------------------------------------
__device__ __forceinline__ uint32_t smem_u32(const void* p) {
    uint32_t a;
    asm("{ .reg .u64 t; cvta.to.shared.u64 t, %1; cvt.u32.u64 %0, t; }"
        : "=r"(a) : "l"(p));
    return a;
}
__device__ __forceinline__ void ldm4(uint32_t (&r)[4], uint32_t a) {
    asm volatile("ldmatrix.sync.aligned.m8n8.x4.shared.b16 {%0,%1,%2,%3}, [%4];"
        : "=r"(r[0]), "=r"(r[1]), "=r"(r[2]), "=r"(r[3]) : "r"(a));
}
__device__ __forceinline__ void mma16816(float* c, const uint32_t* a,
                                         uint32_t b0, uint32_t b1) {
    asm volatile("mma.sync.aligned.m16n8k16.row.col.f32.f16.f16.f32 "
        "{%0,%1,%2,%3}, {%4,%5,%6,%7}, {%8,%9}, {%0,%1,%2,%3};"
        : "+f"(c[0]), "+f"(c[1]), "+f"(c[2]), "+f"(c[3])
        : "r"(a[0]), "r"(a[1]), "r"(a[2]), "r"(a[3]), "r"(b0), "r"(b1));
}
__device__ __forceinline__ void cpasync16(uint32_t s, const void* g) {
    asm volatile("cp.async.cg.shared.global [%0], [%1], 16;" :: "r"(s), "l"(g));
}
// merged-plane helper: m = fl16(32x - 31*h)
__device__ __forceinline__ __half mk_m(float x, __half h) {
    return __float2half(32.0f * x - 31.0f * __half2float(h));
}

// ---------------- plain fp16 HMMA GEMM -------------------------------------
// C[M,N] = A[M,K] @ B[N,K]^T, both K-major. CTA tile 128x128, 8 warps
// (warp tile 32x64), K-tile 64, 2-stage cp.async double buffer.
// Row stride 144B (64 halves + 16B pad): 144/16 = 9 is odd -> ldmatrix
// conflict-free across 8-row groups.
// EPI 0: store fp32 C.
// EPI 2: transposed fp16 hi per batch of 2048 rows: Ch[e, s] (ld 2048).
// EPI 3: combine with fp32 S (read via C): t = (31/32)S + acc/32;
//        write Ch = fl16(t), Cl = fl16(32t - 31*Ch).
// EPI 4: combine in place: C = (31/32)C + acc/32 (fp32).
#define OP_BYTES 18432   // 128 rows * 144 B

template <int EPI>
__global__ __launch_bounds__(256, 2) void gemm_hmma(
    const __half* __restrict__ A, const __half* __restrict__ B,
    float* __restrict__ C, __half* __restrict__ Ch, __half* __restrict__ Cl,
    int K, int ldc, long long sA, long long sB, long long sC)
{
    constexpr uint32_t STAGE = 2 * OP_BYTES;   // A, B
    extern __shared__ char smem[];
    const uint32_t sbase = smem_u32(smem);
    const int tid  = threadIdx.x;
    const int lane = tid & 31, wid = tid >> 5;
    const int wm = wid & 3, wn = wid >> 2;   // warp grid 4(m) x 2(n)
    const long long bz = blockIdx.z;
    A += bz * sA; B += bz * sB;
    const int row0 = blockIdx.y * 128;
    const int col0 = blockIdx.x * 128;

    float acc[2][8][4];
#pragma unroll
    for (int i = 0; i < 2; ++i)
#pragma unroll
        for (int j = 0; j < 8; ++j)
#pragma unroll
            for (int q = 0; q < 4; ++q) acc[i][j][q] = 0.0f;

    // stage loader: 2 ops x 128 rows x 8 x 16B chunks = 8 cp.async / thread
    auto load_stage = [&](int st, int k0) {
        const uint32_t base = sbase + st * STAGE;
#pragma unroll
        for (int j = 0; j < 8; ++j) {
            const int op  = j >> 2;                 // 0:A 1:B
            const int idx = ((j & 3) << 8) + tid;   // 0..1023
            const int r = idx >> 3, c = idx & 7;    // row 0..127, 16B chunk 0..7
            const __half* gp = (op == 0) ? A : B;
            const int gr = ((op == 0) ? row0 : col0) + r;
            cpasync16(base + op * OP_BYTES + r * 144 + c * 16,
                      gp + (long long)gr * K + k0 + c * 8);
        }
        asm volatile("cp.async.commit_group;");
    };

    const int ntiles = K >> 6;
    load_stage(0, 0);

    for (int kt = 0; kt < ntiles; ++kt) {
        asm volatile("cp.async.wait_group 0;" ::: "memory");
        __syncthreads();   // math(kt-1) done everywhere AND stage kt visible
        if (kt + 1 < ntiles)
            load_stage((kt + 1) & 1, (kt + 1) << 6);  // overwrites kt-1: safe

        const uint32_t st  = sbase + (kt & 1) * STAGE;
        const uint32_t sA_ = st, sB_ = st + OP_BYTES;
        const uint32_t lrow = (lane & 15) * 144 + (lane >> 4) * 16;

#pragma unroll
        for (int ks = 0; ks < 4; ++ks) {
            uint32_t af[2][4];
#pragma unroll
            for (int mt = 0; mt < 2; ++mt)
                ldm4(af[mt], sA_ + (uint32_t)(wm * 32 + mt * 16) * 144 + ks * 32 + lrow);
#pragma unroll
            for (int p = 0; p < 4; ++p) {
                uint32_t bf[4];
                ldm4(bf, sB_ + (uint32_t)(wn * 64 + p * 16) * 144 + ks * 32 + lrow);
#pragma unroll
                for (int mt = 0; mt < 2; ++mt) {
                    mma16816(acc[mt][2*p],   af[mt], bf[0], bf[2]);
                    mma16816(acc[mt][2*p+1], af[mt], bf[1], bf[3]);
                }
            }
        }
    }
    __syncthreads();

    const int l4 = lane >> 2, l2 = (lane & 3) * 2;

    if (EPI == 2) {
        // Transposed hi-only epilogue: stage tile in smem, write Ch[e, s].
        __half* sst = (__half*)smem;          // stride 130 halves per m-row
        const int b  = row0 >> 11;            // batch (2048 rows per batch)
        const int s0 = row0 & 2047;
#pragma unroll
        for (int mt = 0; mt < 2; ++mt)
#pragma unroll
            for (int nt = 0; nt < 8; ++nt) {
                const int rl = wm * 32 + mt * 16 + l4;
                const int cl = wn * 64 + nt * 8 + l2;
                const float* a = acc[mt][nt];
                *(__half2*)&sst[rl * 130 + cl] =
                    __halves2half2(__float2half(a[0]), __float2half(a[1]));
                *(__half2*)&sst[(rl + 8) * 130 + cl] =
                    __halves2half2(__float2half(a[2]), __float2half(a[3]));
            }
        __syncthreads();
#pragma unroll
        for (int j = 0; j < 16; ++j) {
            const int e = j * 8 + wid;
            __half v[4];
#pragma unroll
            for (int q = 0; q < 4; ++q)
                v[q] = sst[(4 * lane + q) * 130 + e];
            const long long o = (long long)b * (1024LL * 2048) +
                                (long long)(col0 + e) * 2048 + s0 + 4 * lane;
            *(uint2*)(Ch + o) = *(uint2*)v;
        }
        return;
    }

#pragma unroll
    for (int mt = 0; mt < 2; ++mt) {
#pragma unroll
        for (int nt = 0; nt < 8; ++nt) {
            const int r  = row0 + wm * 32 + mt * 16 + l4;
            const int cc = col0 + wn * 64 + nt * 8 + l2;
            const long long o0 = bz * sC + (long long)r * ldc + cc;
            const long long o1 = o0 + 8LL * ldc;
            const float* a = acc[mt][nt];
            if (EPI == 0) {
                *(float2*)(C + o0) = make_float2(a[0], a[1]);
                *(float2*)(C + o1) = make_float2(a[2], a[3]);
            } else if (EPI == 4) {
                float2 s0v = *(float2*)(C + o0);
                float2 s1v = *(float2*)(C + o1);
                *(float2*)(C + o0) = make_float2(
                    0.96875f * s0v.x + 0.03125f * a[0],
                    0.96875f * s0v.y + 0.03125f * a[1]);
                *(float2*)(C + o1) = make_float2(
                    0.96875f * s1v.x + 0.03125f * a[2],
                    0.96875f * s1v.y + 0.03125f * a[3]);
            } else {  // EPI == 3: combine + emit (h, m) planes
                const float2 s0v = *(const float2*)(C + o0);
                const float2 s1v = *(const float2*)(C + o1);
                const float t0 = 0.96875f * s0v.x + 0.03125f * a[0];
                const float t1 = 0.96875f * s0v.y + 0.03125f * a[1];
                const float t2 = 0.96875f * s1v.x + 0.03125f * a[2];
                const float t3 = 0.96875f * s1v.y + 0.03125f * a[3];
                const __half h0 = __float2half(t0), h1 = __float2half(t1);
                const __half h2 = __float2half(t2), h3 = __float2half(t3);
                *(__half2*)(Ch + o0) = __halves2half2(h0, h1);
                *(__half2*)(Ch + o1) = __halves2half2(h2, h3);
                *(__half2*)(Cl + o0) = __halves2half2(mk_m(t0, h0), mk_m(t1, h1));
                *(__half2*)(Cl + o1) = __halves2half2(mk_m(t2, h2), mk_m(t3, h3));
            }
        }
    }
}

// ---------------- fused fp32 -> (h, m) planes for all 4 inputs -------------
// blocks [0,8192): rnn   [8192,16384): Lt   [16384,16896): W   [16896,17408): k0
__global__ __launch_bounds__(256) void split_all_kernel(
    const float* __restrict__ rnn, const float* __restrict__ Lt,
    const float* __restrict__ W,   const float* __restrict__ k0,
    __half* __restrict__ rnnh, __half* __restrict__ rnnm,
    __half* __restrict__ lth,  __half* __restrict__ ltm,
    __half* __restrict__ wh,   __half* __restrict__ wm,
    __half* __restrict__ k0h,  __half* __restrict__ k0m)
{
    const float* x; __half *h, *m;
    long long blk = blockIdx.x;
    if (blk < 8192)       { x = rnn; h = rnnh; m = rnnm; }
    else if (blk < 16384) { x = Lt;  h = lth;  m = ltm;  blk -= 8192; }
    else if (blk < 16896) { x = W;   h = wh;   m = wm;   blk -= 16384; }
    else                  { x = k0;  h = k0h;  m = k0m;  blk -= 16896; }

    const long long i0 = (blk * 256 + threadIdx.x) * 8;
#pragma unroll
    for (int v = 0; v < 2; ++v) {
        const float4 f = *(const float4*)(x + i0 + v * 4);
        const float ff[4] = {f.x, f.y, f.z, f.w};
        __half hh[4], mm[4];
#pragma unroll
        for (int j = 0; j < 4; ++j) {
            hh[j] = __float2half(ff[j]);
            mm[j] = mk_m(ff[j], hh[j]);
        }
        *(uint2*)(h + i0 + v * 4) = *(uint2*)hh;
        *(uint2*)(m + i0 + v * 4) = *(uint2*)mm;
    }
}

// ---------------- fp32 [R,C] -> transposed fp16 hi [C,R] -------------------
__global__ __launch_bounds__(256) void splitT_kernel(
    const float* __restrict__ in, __half* __restrict__ oh, int R, int C)
{
    __shared__ float t[32][33];
    const int c0 = blockIdx.x * 32, r0 = blockIdx.y * 32;
    const int tx = threadIdx.x & 31, ty = threadIdx.x >> 5;  // 32 x 8
#pragma unroll
    for (int i = 0; i < 4; ++i)
        t[ty + 8 * i][tx] = in[(long long)(r0 + ty + 8 * i) * C + c0 + tx];
    __syncthreads();
#pragma unroll
    for (int i = 0; i < 4; ++i) {
        const long long o = (long long)(c0 + ty + 8 * i) * R + r0 + tx;
        oh[o] = __float2half(t[tx][ty + 8 * i]);
    }
}

// ---------------- softmax rows (2048) + fp16 hi write ----------------------
__global__ __launch_bounds__(256) void softmax_split_kernel(
    float* __restrict__ data, __half* __restrict__ wh, float scale)
{
    __shared__ float sred[256];
    const int tid = threadIdx.x;
    const long long rb = (long long)blockIdx.x * 2048;
    float* row = data + rb;

    float v[8];
    float m = -1e30f;
#pragma unroll
    for (int i = 0; i < 8; ++i) {
        v[i] = row[i * 256 + tid] * scale;
        m = fmaxf(m, v[i]);
    }
    sred[tid] = m;
    __syncthreads();
    for (int s = 128; s > 0; s >>= 1) {
        if (tid < s) sred[tid] = fmaxf(sred[tid], sred[tid + s]);
        __syncthreads();
    }
    m = sred[0];
    __syncthreads();

    float sum = 0.0f;
#pragma unroll
    for (int i = 0; i < 8; ++i) {
        v[i] = expf(v[i] - m);
        sum += v[i];
    }
    sred[tid] = sum;
    __syncthreads();
    for (int s = 128; s > 0; s >>= 1) {
        if (tid < s) sred[tid] += sred[tid + s];
        __syncthreads();
    }
    const float inv = 1.0f / sred[0];
#pragma unroll
    for (int i = 0; i < 8; ++i) {
        const float w = v[i] * inv;
        row[i * 256 + tid] = w;
        wh[rb + i * 256 + tid] = __float2half(w);
    }
}

// ---------------------------------------------------------------------------
extern "C" void kernel_launch(void* const* d_in, const int* in_sizes, int n_in,
                              void* d_out, int out_size)
{
    const float* Lt   = (const float*)d_in[0];   // [8, 2048, 1024]
    const float* rnn  = (const float*)d_in[1];   // [8, 2048, 1024]
    const float* kern = (const float*)d_in[2];   // [2, 1024, 1024]
    const float* W    = (const float*)d_in[3];   // [1024, 1024]

    float* ctx = (float*)d_out;                  // [8, 2048, 1024]
    float* wts = (float*)d_out + CTX_ELEMS;      // [8, 2048, 2048]

    __half *rnnh, *rnnm, *lth, *ltm, *wWh, *wWm, *k0h, *k0m, *k1th;
    __half *Ph, *Pm, *Th, *Tm, *wvth, *wh;
    float *PS, *TS;
    cudaGetSymbolAddress((void**)&rnnh, g_rnn_h); cudaGetSymbolAddress((void**)&rnnm, g_rnn_m);
    cudaGetSymbolAddress((void**)&lth,  g_Lt_h);  cudaGetSymbolAddress((void**)&ltm,  g_Lt_m);
    cudaGetSymbolAddress((void**)&wWh,  g_W_h);   cudaGetSymbolAddress((void**)&wWm,  g_W_m);
    cudaGetSymbolAddress((void**)&k0h,  g_k0_h);  cudaGetSymbolAddress((void**)&k0m,  g_k0_m);
    cudaGetSymbolAddress((void**)&k1th, g_k1t_h);
    cudaGetSymbolAddress((void**)&Ph,   g_P_h);   cudaGetSymbolAddress((void**)&Pm,   g_P_m);
    cudaGetSymbolAddress((void**)&PS,   g_PS);
    cudaGetSymbolAddress((void**)&Th,   g_T_h);   cudaGetSymbolAddress((void**)&Tm,   g_T_m);
    cudaGetSymbolAddress((void**)&TS,   g_TS);
    cudaGetSymbolAddress((void**)&wvth, g_WVt_h);
    cudaGetSymbolAddress((void**)&wh,   g_w_h);

    const int SMEM = 2 * 2 * OP_BYTES;  // 73728
    cudaFuncSetAttribute(gemm_hmma<0>, cudaFuncAttributeMaxDynamicSharedMemorySize, SMEM);
    cudaFuncSetAttribute(gemm_hmma<2>, cudaFuncAttributeMaxDynamicSharedMemorySize, SMEM);
    cudaFuncSetAttribute(gemm_hmma<3>, cudaFuncAttributeMaxDynamicSharedMemorySize, SMEM);
    cudaFuncSetAttribute(gemm_hmma<4>, cudaFuncAttributeMaxDynamicSharedMemorySize, SMEM);

    // 0) (h, m) planes for rnn/Lt/W/k0 + k1 transpose (hi only)
    split_all_kernel<<<17408, 256>>>(rnn, Lt, W, kern,
                                     rnnh, rnnm, lth, ltm,
                                     wWh, wWm, k0h, k0m);
    splitT_kernel<<<dim3(32, 32, 1), 256>>>(kern + 1024 * 1024, k1th, 1024, 1024);

    // 1) P = k0 @ W^T : S pass then M pass (combine -> Ph, Pm)
    gemm_hmma<0><<<dim3(8, 8, 1), 256, SMEM>>>(
        k0h, wWh, PS, nullptr, nullptr, 1024, 1024, 0, 0, 0);
    gemm_hmma<3><<<dim3(8, 8, 1), 256, SMEM>>>(
        k0m, wWm, PS, Ph, Pm, 1024, 1024, 0, 0, 0);

    // 2) T = rnn @ P^T : S pass then M pass (combine -> Th, Tm)
    gemm_hmma<0><<<dim3(8, 128, 1), 256, SMEM>>>(
        rnnh, Ph, TS, nullptr, nullptr, 1024, 1024, 0, 0, 0);
    gemm_hmma<3><<<dim3(8, 128, 1), 256, SMEM>>>(
        rnnm, Pm, TS, Th, Tm, 1024, 1024, 0, 0, 0);

    // 3) WVt = (Lt @ k1)^T per batch (hi-only, fused transpose)
    gemm_hmma<2><<<dim3(8, 128, 1), 256, SMEM>>>(
        lth, k1th, nullptr, wvth, nullptr, 1024, 0, 0, 0, 0);

    // 4) QK: S pass -> wts (fp32), M pass combines in place
    gemm_hmma<0><<<dim3(16, 16, 8), 256, SMEM>>>(
        Th, lth, wts, nullptr, nullptr, 1024, 2048,
        2048LL * 1024, 2048LL * 1024, 2048LL * 2048);
    gemm_hmma<4><<<dim3(16, 16, 8), 256, SMEM>>>(
        Tm, ltm, wts, nullptr, nullptr, 1024, 2048,
        2048LL * 1024, 2048LL * 1024, 2048LL * 2048);

    // 5) softmax(QK * 0.125) in place + fp16 hi for context GEMM
    softmax_split_kernel<<<16384, 256>>>(wts, wh, 0.125f);

    // 6) ctx = weights @ WVt^T per batch, K=2048
    gemm_hmma<0><<<dim3(8, 16, 8), 256, SMEM>>>(
        wh, wvth, ctx, nullptr, nullptr, 2048, 1024,
        2048LL * 2048, 1024LL * 2048, 2048LL * 1024);
}